// round 1
// baseline (speedup 1.0000x reference)
#include <cuda_runtime.h>
#include <math.h>

// Problem constants
#define BB  2
#define SS  2048
#define EE  2048
#define HH  16
#define DHH 128
#define LL  64
#define MM  (BB*SS)          // 4096 rows for the big GEMMs

#define N_BSE ((size_t)BB*SS*EE)       // 8388608
#define N_LAT ((size_t)BB*HH*SS*LL)    // 4194304

// Scratch: q, k, v, attn_out, mixed (5x N_BSE) + q_lat, k_lat (2x N_LAT)  ~192MB
__device__ float g_scratch[5*8388608 + 2*4194304];

// ---------------------------------------------------------------------------
// SGEMM + bias: C[M,N] = A[M,K] @ W[K,N] + b   (row-major, fp32)
// 128x128 block tile, BK=16, 256 threads, 8x8 microtile.
// ---------------------------------------------------------------------------
__global__ __launch_bounds__(256, 2)
void sgemm_bias(const float* __restrict__ A, const float* __restrict__ W,
                const float* __restrict__ bias, float* __restrict__ C,
                int M, int N, int K) {
    __shared__ float As[16][132];   // transposed: As[k][m]
    __shared__ float Bs[16][132];   // Bs[k][n]

    const int tid = threadIdx.x;
    const int tx = tid & 15, ty = tid >> 4;
    const int m0 = blockIdx.y * 128, n0 = blockIdx.x * 128;

    const int am = tid >> 1;            // 0..127
    const int ak = (tid & 1) * 8;       // 0 or 8
    const int bk = tid >> 4;            // 0..15
    const int bn = (tid & 15) * 8;      // 0..120

    const float* Ap = A + (size_t)(m0 + am) * K + ak;
    const float* Wp = W + (size_t)bk * N + n0 + bn;

    float acc[8][8];
#pragma unroll
    for (int i = 0; i < 8; i++)
#pragma unroll
        for (int j = 0; j < 8; j++) acc[i][j] = 0.f;

    for (int k0 = 0; k0 < K; k0 += 16) {
        float4 a0 = *(const float4*)(Ap + k0);
        float4 a1 = *(const float4*)(Ap + k0 + 4);
        float4 b0 = *(const float4*)(Wp + (size_t)k0 * N);
        float4 b1 = *(const float4*)(Wp + (size_t)k0 * N + 4);
        __syncthreads();   // protect previous iteration's reads
        As[ak+0][am] = a0.x; As[ak+1][am] = a0.y; As[ak+2][am] = a0.z; As[ak+3][am] = a0.w;
        As[ak+4][am] = a1.x; As[ak+5][am] = a1.y; As[ak+6][am] = a1.z; As[ak+7][am] = a1.w;
        *(float4*)&Bs[bk][bn]     = b0;
        *(float4*)&Bs[bk][bn + 4] = b1;
        __syncthreads();
#pragma unroll
        for (int kk = 0; kk < 16; kk++) {
            float af[8], bf[8];
            *(float4*)&af[0] = *(const float4*)&As[kk][ty*8];
            *(float4*)&af[4] = *(const float4*)&As[kk][ty*8 + 4];
            *(float4*)&bf[0] = *(const float4*)&Bs[kk][tx*8];
            *(float4*)&bf[4] = *(const float4*)&Bs[kk][tx*8 + 4];
#pragma unroll
            for (int i = 0; i < 8; i++)
#pragma unroll
                for (int j = 0; j < 8; j++) acc[i][j] += af[i] * bf[j];
        }
    }

    float bv[8];
    *(float4*)&bv[0] = *(const float4*)&bias[n0 + tx*8];
    *(float4*)&bv[4] = *(const float4*)&bias[n0 + tx*8 + 4];
#pragma unroll
    for (int i = 0; i < 8; i++) {
        float* cp = C + (size_t)(m0 + ty*8 + i) * N + n0 + tx*8;
        float4 o0, o1;
        o0.x = acc[i][0] + bv[0]; o0.y = acc[i][1] + bv[1];
        o0.z = acc[i][2] + bv[2]; o0.w = acc[i][3] + bv[3];
        o1.x = acc[i][4] + bv[4]; o1.y = acc[i][5] + bv[5];
        o1.z = acc[i][6] + bv[6]; o1.w = acc[i][7] + bv[7];
        *(float4*)cp       = o0;
        *(float4*)(cp + 4) = o1;
    }
}

// ---------------------------------------------------------------------------
// Latent projection + elu+1:
//   lat[b,h,s,l] = elu( proj[b,s,h*DH : (h+1)*DH] @ Wl[DH,L] + bl[l] ) + 1
// One block per (b,s); 256 threads; each thread does 4 heads x 1 latent col.
// ---------------------------------------------------------------------------
__global__ __launch_bounds__(256)
void latent_kernel(const float* __restrict__ proj, const float* __restrict__ Wl,
                   const float* __restrict__ bl, float* __restrict__ lat) {
    __shared__ float w_s[DHH * LL];   // 32KB
    __shared__ float row_s[EE];       // 8KB
    __shared__ float b_s[LL];

    const int tid = threadIdx.x;
    const int bidx = blockIdx.x;          // b*S + s
    const int b = bidx / SS, s = bidx % SS;

    for (int i = tid; i < DHH * LL; i += 256) w_s[i] = Wl[i];
    for (int i = tid; i < EE; i += 256)       row_s[i] = proj[(size_t)bidx * EE + i];
    if (tid < LL) b_s[tid] = bl[tid];
    __syncthreads();

    const int l = tid & 63;
    const int hb = tid >> 6;              // 0..3
#pragma unroll
    for (int i = 0; i < 4; i++) {
        const int h = hb * 4 + i;
        float acc = b_s[l];
        const float* rp = &row_s[h * DHH];
#pragma unroll 8
        for (int d = 0; d < DHH; d++) acc += rp[d] * w_s[d * LL + l];
        float r = (acc > 0.f) ? (acc + 1.f) : __expf(acc);
        lat[(((size_t)b * HH + h) * SS + s) * LL + l] = r;
    }
}

// ---------------------------------------------------------------------------
// Block attention. grid = (S/64, H, B); 256 threads.
// Per block: 64 q rows. For each of 4 kv blocks (512 keys): full scores in
// smem, exact softmax over 512, then accumulate P@V into registers.
// ---------------------------------------------------------------------------
#define ATT_SMEM_BYTES ((64*68 + 64*132 + 64*516 + 512 + 64) * 4)

__global__ __launch_bounds__(256, 1)
void attention_kernel(const float* __restrict__ qlat, const float* __restrict__ klat,
                      const float* __restrict__ v, float* __restrict__ outp) {
    extern __shared__ float sm[];
    float* q_s  = sm;                    // [64][68]
    float* kv_s = sm + 64*68;            // [64][132] union: kT chunk / v chunk
    float* s_s  = kv_s + 64*132;         // [64][516] scores/probs for one kv block
    float* red  = s_s + 64*516;          // 512 reduction slots
    float* linv = red + 512;             // 64 inverse row sums

    const int tid = threadIdx.x;
    const int tx = tid & 15, ty = tid >> 4;
    const int qt = blockIdx.x, h = blockIdx.y, b = blockIdx.z;
    const int qr0 = qt * 64;

    const float* qb = qlat + ((size_t)(b*HH + h) * SS + qr0) * LL;
    const float* kb = klat + (size_t)(b*HH + h) * SS * LL;
    const float* vb = v + (size_t)b * SS * EE + h * DHH;

    // load q tile [64][64]
    {
        int r = tid >> 2, c = (tid & 3) * 16;
#pragma unroll
        for (int j = 0; j < 16; j += 4)
            *(float4*)&q_s[r*68 + c + j] = *(const float4*)(qb + (size_t)r*LL + c + j);
    }

    float out[4][8];
#pragma unroll
    for (int i = 0; i < 4; i++)
#pragma unroll
        for (int j = 0; j < 8; j++) out[i][j] = 0.f;

    const int r0 = ty * 4, c0 = tx * 8;

    for (int kvb = 0; kvb < 4; kvb++) {
        const int f00 = kvb * 512;

        // ---- scores: s_s[64][512] = 0.125 * q @ k^T ----
        for (int kc = 0; kc < 4; kc++) {
            __syncthreads();   // kv_s free to overwrite
            {
                int f = tid >> 1, l0 = (tid & 1) * 32;
                const float* kp = kb + (size_t)(f00 + kc*128 + f) * LL + l0;
#pragma unroll
                for (int j = 0; j < 32; j += 4) {
                    float4 t4 = *(const float4*)(kp + j);
                    kv_s[(l0+j+0)*132 + f] = t4.x;
                    kv_s[(l0+j+1)*132 + f] = t4.y;
                    kv_s[(l0+j+2)*132 + f] = t4.z;
                    kv_s[(l0+j+3)*132 + f] = t4.w;
                }
            }
            __syncthreads();
            float acc[4][8];
#pragma unroll
            for (int i = 0; i < 4; i++)
#pragma unroll
                for (int j = 0; j < 8; j++) acc[i][j] = 0.f;
#pragma unroll 8
            for (int l = 0; l < 64; l++) {
                float qv[4], kf[8];
#pragma unroll
                for (int i = 0; i < 4; i++) qv[i] = q_s[(r0+i)*68 + l];
                *(float4*)&kf[0] = *(const float4*)&kv_s[l*132 + c0];
                *(float4*)&kf[4] = *(const float4*)&kv_s[l*132 + c0 + 4];
#pragma unroll
                for (int i = 0; i < 4; i++)
#pragma unroll
                    for (int j = 0; j < 8; j++) acc[i][j] += qv[i] * kf[j];
            }
#pragma unroll
            for (int i = 0; i < 4; i++) {
                float* sp = &s_s[(r0+i)*516 + kc*128 + c0];
                float4 o0, o1;
                o0.x = acc[i][0]*0.125f; o0.y = acc[i][1]*0.125f;
                o0.z = acc[i][2]*0.125f; o0.w = acc[i][3]*0.125f;
                o1.x = acc[i][4]*0.125f; o1.y = acc[i][5]*0.125f;
                o1.z = acc[i][6]*0.125f; o1.w = acc[i][7]*0.125f;
                *(float4*)sp       = o0;
                *(float4*)(sp + 4) = o1;
            }
        }
        __syncthreads();

        // ---- exact softmax over 512 per row (4 threads per row) ----
        {
            const int row = tid >> 2, seg = tid & 3;
            float* srow = &s_s[row*516 + seg*128];
            float mx = -3.0e38f;
            for (int i = 0; i < 128; i++) mx = fmaxf(mx, srow[i]);
            red[row*4 + seg] = mx;
            __syncthreads();
            float m = fmaxf(fmaxf(red[row*4+0], red[row*4+1]),
                            fmaxf(red[row*4+2], red[row*4+3]));
            float sumv = 0.f;
            for (int i = 0; i < 128; i++) {
                float e = __expf(srow[i] - m);
                srow[i] = e;
                sumv += e;
            }
            red[256 + row*4 + seg] = sumv;
            __syncthreads();
            if (seg == 0) {
                float ls = red[256+row*4] + red[256+row*4+1] +
                           red[256+row*4+2] + red[256+row*4+3];
                linv[row] = 1.0f / ls;
            }
        }
        __syncthreads();

        // ---- out += (P / l) @ V  (v streamed in 8 chunks of 64 rows) ----
        for (int vc = 0; vc < 8; vc++) {
            {
                int f = tid >> 2, d0 = (tid & 3) * 32;
                const float* vp = vb + (size_t)(f00 + vc*64 + f) * EE + d0;
#pragma unroll
                for (int j = 0; j < 32; j += 4)
                    *(float4*)&kv_s[f*132 + d0 + j] = *(const float4*)(vp + j);
            }
            __syncthreads();
            float lv[4];
#pragma unroll
            for (int i = 0; i < 4; i++) lv[i] = linv[r0 + i];
#pragma unroll 8
            for (int f = 0; f < 64; f++) {
                float pv[4], vf[8];
#pragma unroll
                for (int i = 0; i < 4; i++)
                    pv[i] = s_s[(r0+i)*516 + vc*64 + f] * lv[i];
                *(float4*)&vf[0] = *(const float4*)&kv_s[f*132 + c0];
                *(float4*)&vf[4] = *(const float4*)&kv_s[f*132 + c0 + 4];
#pragma unroll
                for (int i = 0; i < 4; i++)
#pragma unroll
                    for (int j = 0; j < 8; j++) out[i][j] += pv[i] * vf[j];
            }
            __syncthreads();
        }
    }

    float* op = outp + ((size_t)(b*HH + h) * SS + qr0) * DHH;
#pragma unroll
    for (int i = 0; i < 4; i++) {
        float4 o0, o1;
        o0.x = out[i][0]; o0.y = out[i][1]; o0.z = out[i][2]; o0.w = out[i][3];
        o1.x = out[i][4]; o1.y = out[i][5]; o1.z = out[i][6]; o1.w = out[i][7];
        *(float4*)&op[(r0+i)*DHH + c0]     = o0;
        *(float4*)&op[(r0+i)*DHH + c0 + 4] = o1;
    }
}

// ---------------------------------------------------------------------------
// Mixer: mixed[b,s,h*DH+d] = gelu( attn[b,h,s,:] @ Wm[DH,DH] + bm[d] )
// One block per 16 rows of attn ([B,H,S] flattened); 256 threads.
// ---------------------------------------------------------------------------
#define MIX_SMEM_BYTES ((128*130 + 16*128) * 4)

__device__ __forceinline__ float gelu_tanh(float x) {
    float x3 = x * x * x;
    return 0.5f * x * (1.f + tanhf(0.7978845608028654f * (x + 0.044715f * x3)));
}

__global__ __launch_bounds__(256)
void mixer_kernel(const float* __restrict__ attn, const float* __restrict__ Wm,
                  const float* __restrict__ bm, float* __restrict__ mixed) {
    extern __shared__ float sm[];
    float* wm_s = sm;              // [128][130]
    float* in_s = sm + 128*130;    // [16][128]

    const int tid = threadIdx.x;
    const int R0 = blockIdx.x * 16;

    for (int i = tid; i < DHH*DHH; i += 256) {
        int d = i >> 7, c = i & 127;
        wm_s[d*130 + c] = Wm[i];
    }
    for (int i = tid; i < 16*DHH; i += 256)
        in_s[i] = attn[(size_t)R0 * DHH + i];
    __syncthreads();

    const int cp = (tid & 63) * 2;   // column pair
    const int rg = tid >> 6;         // 0..3 -> rows rg*4..rg*4+3

    float acc[4][2];
#pragma unroll
    for (int i = 0; i < 4; i++) { acc[i][0] = 0.f; acc[i][1] = 0.f; }

#pragma unroll 8
    for (int d = 0; d < 128; d++) {
        float w0 = wm_s[d*130 + cp], w1 = wm_s[d*130 + cp + 1];
#pragma unroll
        for (int i = 0; i < 4; i++) {
            float a = in_s[(rg*4 + i)*128 + d];
            acc[i][0] += a * w0;
            acc[i][1] += a * w1;
        }
    }

    float b0 = bm[cp], b1 = bm[cp + 1];
#pragma unroll
    for (int i = 0; i < 4; i++) {
        int R = R0 + rg*4 + i;                    // ((b*H + h)*S + s)
        int b = R / (HH*SS);
        int rem = R % (HH*SS);
        int h = rem / SS, s = rem % SS;
        float2 o;
        o.x = gelu_tanh(acc[i][0] + b0);
        o.y = gelu_tanh(acc[i][1] + b1);
        *(float2*)&mixed[((size_t)b*SS + s)*EE + h*DHH + cp] = o;
    }
}

// ---------------------------------------------------------------------------
// Launch
// ---------------------------------------------------------------------------
extern "C" void kernel_launch(void* const* d_in, const int* in_sizes, int n_in,
                              void* d_out, int out_size) {
    const float* x   = (const float*)d_in[0];
    const float* Wq  = (const float*)d_in[1];
    const float* bq  = (const float*)d_in[2];
    const float* Wk  = (const float*)d_in[3];
    const float* bk_ = (const float*)d_in[4];
    const float* Wv  = (const float*)d_in[5];
    const float* bv_ = (const float*)d_in[6];
    const float* Wo  = (const float*)d_in[7];
    const float* bo  = (const float*)d_in[8];
    const float* Wql = (const float*)d_in[9];
    const float* bql = (const float*)d_in[10];
    const float* Wkl = (const float*)d_in[11];
    const float* bkl = (const float*)d_in[12];
    const float* Wm  = (const float*)d_in[13];
    const float* bm  = (const float*)d_in[14];
    float* outp = (float*)d_out;

    float* base = nullptr;
    cudaGetSymbolAddress((void**)&base, g_scratch);
    float* q    = base;
    float* k    = base + N_BSE;
    float* vv   = base + 2*N_BSE;
    float* attn = base + 3*N_BSE;
    float* mixd = base + 4*N_BSE;
    float* qlat = base + 5*N_BSE;
    float* klat = base + 5*N_BSE + N_LAT;

    cudaFuncSetAttribute(attention_kernel,
        cudaFuncAttributeMaxDynamicSharedMemorySize, ATT_SMEM_BYTES);
    cudaFuncSetAttribute(mixer_kernel,
        cudaFuncAttributeMaxDynamicSharedMemorySize, MIX_SMEM_BYTES);

    dim3 gg(EE/128, MM/128);   // (16, 32)
    sgemm_bias<<<gg, 256>>>(x, Wq, bq,  q,  MM, EE, EE);
    sgemm_bias<<<gg, 256>>>(x, Wk, bk_, k,  MM, EE, EE);
    sgemm_bias<<<gg, 256>>>(x, Wv, bv_, vv, MM, EE, EE);

    latent_kernel<<<BB*SS, 256>>>(q, Wql, bql, qlat);
    latent_kernel<<<BB*SS, 256>>>(k, Wkl, bkl, klat);

    attention_kernel<<<dim3(SS/64, HH, BB), 256, ATT_SMEM_BYTES>>>(qlat, klat, vv, attn);

    mixer_kernel<<<(BB*HH*SS)/16, 256, MIX_SMEM_BYTES>>>(attn, Wm, bm, mixd);

    sgemm_bias<<<gg, 256>>>(mixd, Wo, bo, outp, MM, EE, EE);
}

// round 3
// speedup vs baseline: 1.4407x; 1.4407x over previous
#include <cuda_runtime.h>
#include <cuda_bf16.h>
#include <math.h>
#include <stdint.h>

// Problem constants
#define BB  2
#define SS  2048
#define EE  2048
#define HH  16
#define DHH 128
#define LL  64
#define MM  (BB*SS)          // 4096 rows for the big GEMMs

#define N_BSE ((size_t)BB*SS*EE)       // 8388608
#define N_LAT ((size_t)BB*HH*SS*LL)    // 4194304

// fp32 scratch: q, k, v, attn_out, mixed (5x N_BSE) + q_lat, k_lat (2x N_LAT)
__device__ float g_scratch[5*8388608 + 2*4194304];
// bf16 split-stacked operands: A' [4096, 6144], 4x W'^T [2048, 6144]
__device__ __nv_bfloat16 g_abf[(size_t)4096 * 6144];
__device__ __nv_bfloat16 g_wbf[4][(size_t)2048 * 6144];

// ===========================================================================
// Helpers
// ===========================================================================
__device__ __forceinline__ uint32_t smem_u32(const void* p) {
    uint32_t a;
    asm("{ .reg .u64 t; cvta.to.shared.u64 t, %1; cvt.u32.u64 %0, t; }"
        : "=r"(a) : "l"(p));
    return a;
}

#define CP_ASYNC16(sm, gp) \
    asm volatile("cp.async.cg.shared.global [%0], [%1], 16;" \
        :: "r"((uint32_t)(sm)), "l"(gp) : "memory")
#define CP_COMMIT() asm volatile("cp.async.commit_group;" ::: "memory")
#define CP_WAIT(n)  asm volatile("cp.async.wait_group %0;" :: "n"(n) : "memory")

// SW64 swizzle for 64-byte rows (8-row atom), conflict-free for 16B accesses
#define SWZ64(o) ((o) ^ (((o) >> 3) & 0x30))

#define LDMATRIX_X4(r0, r1, r2, r3, addr) \
    asm volatile("ldmatrix.sync.aligned.m8n8.x4.shared.b16 {%0,%1,%2,%3}, [%4];" \
        : "=r"(r0), "=r"(r1), "=r"(r2), "=r"(r3) : "r"(addr))

#define MMA_BF16(c, a, b) \
    asm volatile("mma.sync.aligned.m16n8k16.row.col.f32.bf16.bf16.f32 " \
        "{%0,%1,%2,%3}, {%4,%5,%6,%7}, {%8,%9}, {%0,%1,%2,%3};" \
        : "+f"((c)[0]), "+f"((c)[1]), "+f"((c)[2]), "+f"((c)[3]) \
        : "r"((a)[0]), "r"((a)[1]), "r"((a)[2]), "r"((a)[3]), \
          "r"((b)[0]), "r"((b)[1]))

// ===========================================================================
// Conversion kernels: fp32 -> bf16 hi/lo, split-stacked along K' = 6144
// ===========================================================================
#define GK  6144
#define GKB (GK * 2)   // row stride in bytes

// A' [M, 6144]: cols [0:2048)=hi, [2048:4096)=hi, [4096:6144)=lo
__global__ __launch_bounds__(256)
void conv_a(const float* __restrict__ in, __nv_bfloat16* __restrict__ out) {
    int i4 = (blockIdx.x * 256 + threadIdx.x) * 4;
    int m = i4 >> 11, k = i4 & 2047;
    float4 xv = *(const float4*)(in + (size_t)m * 2048 + k);
    __nv_bfloat16 h[4], l[4];
    float xs[4] = {xv.x, xv.y, xv.z, xv.w};
#pragma unroll
    for (int j = 0; j < 4; j++) {
        h[j] = __float2bfloat16(xs[j]);
        l[j] = __float2bfloat16(xs[j] - __bfloat162float(h[j]));
    }
    size_t base = (size_t)m * GK + k;
    __nv_bfloat162 h01, h23, l01, l23;
    h01.x = h[0]; h01.y = h[1]; h23.x = h[2]; h23.y = h[3];
    l01.x = l[0]; l01.y = l[1]; l23.x = l[2]; l23.y = l[3];
    *(__nv_bfloat162*)(out + base)            = h01;
    *(__nv_bfloat162*)(out + base + 2)        = h23;
    *(__nv_bfloat162*)(out + base + 2048)     = h01;
    *(__nv_bfloat162*)(out + base + 2050)     = h23;
    *(__nv_bfloat162*)(out + base + 4096)     = l01;
    *(__nv_bfloat162*)(out + base + 4098)     = l23;
}

// W [K=2048, N=2048] -> W'^T [N rows, 6144]: cols [0:2048)=hi, [2048:4096)=lo, [4096:6144)=hi
__global__ __launch_bounds__(256)
void conv_w(const float* __restrict__ W, __nv_bfloat16* __restrict__ out) {
    __shared__ float ts[32][33];
    const int tid = threadIdx.x;
    const int tx = tid & 31, ty = tid >> 5;      // ty 0..7
    const int n0 = blockIdx.x * 32, k0 = blockIdx.y * 32;
#pragma unroll
    for (int it = 0; it < 4; it++)
        ts[ty + it*8][tx] = W[(size_t)(k0 + ty + it*8) * 2048 + n0 + tx];
    __syncthreads();
#pragma unroll
    for (int it = 0; it < 4; it++) {
        int r = ty + it*8;                        // output row n = n0 + r
        float v = ts[tx][r];                      // W[k0+tx, n0+r]
        __nv_bfloat16 hi = __float2bfloat16(v);
        __nv_bfloat16 lo = __float2bfloat16(v - __bfloat162float(hi));
        size_t ob = (size_t)(n0 + r) * GK + k0 + tx;
        out[ob]        = hi;
        out[ob + 2048] = lo;
        out[ob + 4096] = hi;
    }
}

// ===========================================================================
// mma.sync bf16 GEMM: C[4096,2048] = A'[4096,6144] @ W'^T[2048,6144]^T + bias
// 128x128 tile, BK=32, 8 warps (2x4), 4-stage cp.async pipeline, SW64 smem.
// ===========================================================================
#define KITERS   192                       // 6144 / 32
#define STAGE_A  8192                      // 128 rows * 64B
#define STAGE_B  8192
#define B_OFF    (4 * STAGE_A)             // 32768
#define GEMM_SMEM (B_OFF + 4 * STAGE_B)    // 65536

__global__ __launch_bounds__(256, 2)
void gemm_mma(const __nv_bfloat16* __restrict__ A, const __nv_bfloat16* __restrict__ Bt,
              const float* __restrict__ bias, float* __restrict__ C) {
    extern __shared__ char gsm[];
    uint32_t sb = smem_u32(gsm);
    const int tid = threadIdx.x;
    const int wid = tid >> 5, lane = tid & 31;
    const int m0 = blockIdx.y * 128, n0 = blockIdx.x * 128;
    const int wm0 = (wid >> 2) * 64;       // warp m offset in tile
    const int wn0 = (wid & 3) * 32;        // warp n offset in tile

    const char* Ab = (const char*)A + (size_t)m0 * GKB;
    const char* Bb = (const char*)Bt + (size_t)n0 * GKB;

    // per-thread load slots: 2 x 16B for A, 2 x 16B for B per chunk
    const int lr = tid >> 2;               // 0..63 base row
    const int lq = tid & 3;                // quad

    auto load_chunk = [&](int j) {
        const int st = j & 3;
        uint32_t ab = sb + st * STAGE_A;
        uint32_t bb = sb + B_OFF + st * STAGE_B;
        const char* ag = Ab + (size_t)j * 64;
        const char* bg = Bb + (size_t)j * 64;
#pragma unroll
        for (int i = 0; i < 2; i++) {
            int r = lr + i * 64;
            CP_ASYNC16(ab + SWZ64(r * 64 + lq * 16), ag + (size_t)r * GKB + lq * 16);
        }
#pragma unroll
        for (int i = 0; i < 2; i++) {
            int r = lr + i * 64;
            CP_ASYNC16(bb + SWZ64(r * 64 + lq * 16), bg + (size_t)r * GKB + lq * 16);
        }
        CP_COMMIT();
    };

    float acc[4][4][4];
#pragma unroll
    for (int mt = 0; mt < 4; mt++)
#pragma unroll
        for (int nt = 0; nt < 4; nt++)
#pragma unroll
            for (int e = 0; e < 4; e++) acc[mt][nt][e] = 0.f;

    // prologue: stages 0..2
    load_chunk(0);
    load_chunk(1);
    load_chunk(2);

    const int arow = lane & 15;            // ldmatrix row within 16
    const int acol = (lane >> 4) * 16;     // ldmatrix 8-col group (bytes)

    for (int it = 0; it < KITERS; it++) {
        CP_WAIT(2);
        __syncthreads();

        // prefetch next chunk (empty commit keeps group counting uniform)
        if (it + 3 < KITERS) load_chunk(it + 3);
        else                 CP_COMMIT();

        const int st = it & 3;
        uint32_t ab = sb + st * STAGE_A;
        uint32_t bb = sb + B_OFF + st * STAGE_B;

#pragma unroll
        for (int kk = 0; kk < 2; kk++) {
            uint32_t a[4][4];
            uint32_t b[4][2];
#pragma unroll
            for (int mt = 0; mt < 4; mt++) {
                uint32_t addr = ab + SWZ64((wm0 + mt*16 + arow) * 64 + kk*32 + acol);
                LDMATRIX_X4(a[mt][0], a[mt][1], a[mt][2], a[mt][3], addr);
            }
#pragma unroll
            for (int nb = 0; nb < 2; nb++) {
                uint32_t r0, r1, r2, r3;
                uint32_t addr = bb + SWZ64((wn0 + nb*16 + arow) * 64 + kk*32 + acol);
                LDMATRIX_X4(r0, r1, r2, r3, addr);
                b[nb*2+0][0] = r0; b[nb*2+0][1] = r2;
                b[nb*2+1][0] = r1; b[nb*2+1][1] = r3;
            }
#pragma unroll
            for (int mt = 0; mt < 4; mt++)
#pragma unroll
                for (int nt = 0; nt < 4; nt++)
                    MMA_BF16(acc[mt][nt], a[mt], b[nt]);
        }
        __syncthreads();
    }

    // Epilogue: c-frag mapping: rows (lane>>2)+{0,8}, cols (lane&3)*2+{0,1}
    const int er = lane >> 2, ec = (lane & 3) * 2;
#pragma unroll
    for (int mt = 0; mt < 4; mt++) {
#pragma unroll
        for (int nt = 0; nt < 4; nt++) {
            int col = n0 + wn0 + nt*8 + ec;
            float b0 = bias[col], b1 = bias[col + 1];
            int row0 = m0 + wm0 + mt*16 + er;
            float2 o0, o1;
            o0.x = acc[mt][nt][0] + b0; o0.y = acc[mt][nt][1] + b1;
            o1.x = acc[mt][nt][2] + b0; o1.y = acc[mt][nt][3] + b1;
            *(float2*)(C + (size_t)row0 * 2048 + col)       = o0;
            *(float2*)(C + (size_t)(row0 + 8) * 2048 + col) = o1;
        }
    }
}

// ---------------------------------------------------------------------------
// Latent projection + elu+1 (unchanged from R1)
// ---------------------------------------------------------------------------
__global__ __launch_bounds__(256)
void latent_kernel(const float* __restrict__ proj, const float* __restrict__ Wl,
                   const float* __restrict__ bl, float* __restrict__ lat) {
    __shared__ float w_s[DHH * LL];
    __shared__ float row_s[EE];
    __shared__ float b_s[LL];

    const int tid = threadIdx.x;
    const int bidx = blockIdx.x;
    const int b = bidx / SS, s = bidx % SS;

    for (int i = tid; i < DHH * LL; i += 256) w_s[i] = Wl[i];
    for (int i = tid; i < EE; i += 256)       row_s[i] = proj[(size_t)bidx * EE + i];
    if (tid < LL) b_s[tid] = bl[tid];
    __syncthreads();

    const int l = tid & 63;
    const int hb = tid >> 6;
#pragma unroll
    for (int i = 0; i < 4; i++) {
        const int h = hb * 4 + i;
        float acc = b_s[l];
        const float* rp = &row_s[h * DHH];
#pragma unroll 8
        for (int d = 0; d < DHH; d++) acc += rp[d] * w_s[d * LL + l];
        float r = (acc > 0.f) ? (acc + 1.f) : __expf(acc);
        lat[(((size_t)b * HH + h) * SS + s) * LL + l] = r;
    }
}

// ---------------------------------------------------------------------------
// Block attention (unchanged from R1)
// ---------------------------------------------------------------------------
#define ATT_SMEM_BYTES ((64*68 + 64*132 + 64*516 + 512 + 64) * 4)

__global__ __launch_bounds__(256, 1)
void attention_kernel(const float* __restrict__ qlat, const float* __restrict__ klat,
                      const float* __restrict__ v, float* __restrict__ outp) {
    extern __shared__ float sm[];
    float* q_s  = sm;
    float* kv_s = sm + 64*68;
    float* s_s  = kv_s + 64*132;
    float* red  = s_s + 64*516;
    float* linv = red + 512;

    const int tid = threadIdx.x;
    const int tx = tid & 15, ty = tid >> 4;
    const int qt = blockIdx.x, h = blockIdx.y, b = blockIdx.z;
    const int qr0 = qt * 64;

    const float* qb = qlat + ((size_t)(b*HH + h) * SS + qr0) * LL;
    const float* kb = klat + (size_t)(b*HH + h) * SS * LL;
    const float* vb = v + (size_t)b * SS * EE + h * DHH;

    {
        int r = tid >> 2, c = (tid & 3) * 16;
#pragma unroll
        for (int j = 0; j < 16; j += 4)
            *(float4*)&q_s[r*68 + c + j] = *(const float4*)(qb + (size_t)r*LL + c + j);
    }

    float out[4][8];
#pragma unroll
    for (int i = 0; i < 4; i++)
#pragma unroll
        for (int j = 0; j < 8; j++) out[i][j] = 0.f;

    const int r0 = ty * 4, c0 = tx * 8;

    for (int kvb = 0; kvb < 4; kvb++) {
        const int f00 = kvb * 512;

        for (int kc = 0; kc < 4; kc++) {
            __syncthreads();
            {
                int f = tid >> 1, l0 = (tid & 1) * 32;
                const float* kp = kb + (size_t)(f00 + kc*128 + f) * LL + l0;
#pragma unroll
                for (int j = 0; j < 32; j += 4) {
                    float4 t4 = *(const float4*)(kp + j);
                    kv_s[(l0+j+0)*132 + f] = t4.x;
                    kv_s[(l0+j+1)*132 + f] = t4.y;
                    kv_s[(l0+j+2)*132 + f] = t4.z;
                    kv_s[(l0+j+3)*132 + f] = t4.w;
                }
            }
            __syncthreads();
            float acc[4][8];
#pragma unroll
            for (int i = 0; i < 4; i++)
#pragma unroll
                for (int j = 0; j < 8; j++) acc[i][j] = 0.f;
#pragma unroll 8
            for (int l = 0; l < 64; l++) {
                float qv[4], kf[8];
#pragma unroll
                for (int i = 0; i < 4; i++) qv[i] = q_s[(r0+i)*68 + l];
                *(float4*)&kf[0] = *(const float4*)&kv_s[l*132 + c0];
                *(float4*)&kf[4] = *(const float4*)&kv_s[l*132 + c0 + 4];
#pragma unroll
                for (int i = 0; i < 4; i++)
#pragma unroll
                    for (int j = 0; j < 8; j++) acc[i][j] += qv[i] * kf[j];
            }
#pragma unroll
            for (int i = 0; i < 4; i++) {
                float* sp = &s_s[(r0+i)*516 + kc*128 + c0];
                float4 o0, o1;
                o0.x = acc[i][0]*0.125f; o0.y = acc[i][1]*0.125f;
                o0.z = acc[i][2]*0.125f; o0.w = acc[i][3]*0.125f;
                o1.x = acc[i][4]*0.125f; o1.y = acc[i][5]*0.125f;
                o1.z = acc[i][6]*0.125f; o1.w = acc[i][7]*0.125f;
                *(float4*)sp       = o0;
                *(float4*)(sp + 4) = o1;
            }
        }
        __syncthreads();

        {
            const int row = tid >> 2, seg = tid & 3;
            float* srow = &s_s[row*516 + seg*128];
            float mx = -3.0e38f;
            for (int i = 0; i < 128; i++) mx = fmaxf(mx, srow[i]);
            red[row*4 + seg] = mx;
            __syncthreads();
            float m = fmaxf(fmaxf(red[row*4+0], red[row*4+1]),
                            fmaxf(red[row*4+2], red[row*4+3]));
            float sumv = 0.f;
            for (int i = 0; i < 128; i++) {
                float e = __expf(srow[i] - m);
                srow[i] = e;
                sumv += e;
            }
            red[256 + row*4 + seg] = sumv;
            __syncthreads();
            if (seg == 0) {
                float ls = red[256+row*4] + red[256+row*4+1] +
                           red[256+row*4+2] + red[256+row*4+3];
                linv[row] = 1.0f / ls;
            }
        }
        __syncthreads();

        for (int vc = 0; vc < 8; vc++) {
            {
                int f = tid >> 2, d0 = (tid & 3) * 32;
                const float* vp = vb + (size_t)(f00 + vc*64 + f) * EE + d0;
#pragma unroll
                for (int j = 0; j < 32; j += 4)
                    *(float4*)&kv_s[f*132 + d0 + j] = *(const float4*)(vp + j);
            }
            __syncthreads();
            float lv[4];
#pragma unroll
            for (int i = 0; i < 4; i++) lv[i] = linv[r0 + i];
#pragma unroll 8
            for (int f = 0; f < 64; f++) {
                float pv[4], vf[8];
#pragma unroll
                for (int i = 0; i < 4; i++)
                    pv[i] = s_s[(r0+i)*516 + vc*64 + f] * lv[i];
                *(float4*)&vf[0] = *(const float4*)&kv_s[f*132 + c0];
                *(float4*)&vf[4] = *(const float4*)&kv_s[f*132 + c0 + 4];
#pragma unroll
                for (int i = 0; i < 4; i++)
#pragma unroll
                    for (int j = 0; j < 8; j++) out[i][j] += pv[i] * vf[j];
            }
            __syncthreads();
        }
    }

    float* op = outp + ((size_t)(b*HH + h) * SS + qr0) * DHH;
#pragma unroll
    for (int i = 0; i < 4; i++) {
        float4 o0, o1;
        o0.x = out[i][0]; o0.y = out[i][1]; o0.z = out[i][2]; o0.w = out[i][3];
        o1.x = out[i][4]; o1.y = out[i][5]; o1.z = out[i][6]; o1.w = out[i][7];
        *(float4*)&op[(r0+i)*DHH + c0]     = o0;
        *(float4*)&op[(r0+i)*DHH + c0 + 4] = o1;
    }
}

// ---------------------------------------------------------------------------
// Mixer (unchanged from R1)
// ---------------------------------------------------------------------------
#define MIX_SMEM_BYTES ((128*130 + 16*128) * 4)

__device__ __forceinline__ float gelu_tanh(float x) {
    float x3 = x * x * x;
    return 0.5f * x * (1.f + tanhf(0.7978845608028654f * (x + 0.044715f * x3)));
}

__global__ __launch_bounds__(256)
void mixer_kernel(const float* __restrict__ attn, const float* __restrict__ Wm,
                  const float* __restrict__ bm, float* __restrict__ mixed) {
    extern __shared__ float sm[];
    float* wm_s = sm;
    float* in_s = sm + 128*130;

    const int tid = threadIdx.x;
    const int R0 = blockIdx.x * 16;

    for (int i = tid; i < DHH*DHH; i += 256) {
        int d = i >> 7, c = i & 127;
        wm_s[d*130 + c] = Wm[i];
    }
    for (int i = tid; i < 16*DHH; i += 256)
        in_s[i] = attn[(size_t)R0 * DHH + i];
    __syncthreads();

    const int cp = (tid & 63) * 2;
    const int rg = tid >> 6;

    float acc[4][2];
#pragma unroll
    for (int i = 0; i < 4; i++) { acc[i][0] = 0.f; acc[i][1] = 0.f; }

#pragma unroll 8
    for (int d = 0; d < 128; d++) {
        float w0 = wm_s[d*130 + cp], w1 = wm_s[d*130 + cp + 1];
#pragma unroll
        for (int i = 0; i < 4; i++) {
            float a = in_s[(rg*4 + i)*128 + d];
            acc[i][0] += a * w0;
            acc[i][1] += a * w1;
        }
    }

    float b0 = bm[cp], b1 = bm[cp + 1];
#pragma unroll
    for (int i = 0; i < 4; i++) {
        int R = R0 + rg*4 + i;
        int b = R / (HH*SS);
        int rem = R % (HH*SS);
        int h = rem / SS, s = rem % SS;
        float2 o;
        o.x = gelu_tanh(acc[i][0] + b0);
        o.y = gelu_tanh(acc[i][1] + b1);
        *(float2*)&mixed[((size_t)b*SS + s)*EE + h*DHH + cp] = o;
    }
}

// ---------------------------------------------------------------------------
// Launch
// ---------------------------------------------------------------------------
extern "C" void kernel_launch(void* const* d_in, const int* in_sizes, int n_in,
                              void* d_out, int out_size) {
    const float* x   = (const float*)d_in[0];
    const float* Wq  = (const float*)d_in[1];
    const float* bq  = (const float*)d_in[2];
    const float* Wk  = (const float*)d_in[3];
    const float* bk_ = (const float*)d_in[4];
    const float* Wv  = (const float*)d_in[5];
    const float* bv_ = (const float*)d_in[6];
    const float* Wo  = (const float*)d_in[7];
    const float* bo  = (const float*)d_in[8];
    const float* Wql = (const float*)d_in[9];
    const float* bql = (const float*)d_in[10];
    const float* Wkl = (const float*)d_in[11];
    const float* bkl = (const float*)d_in[12];
    const float* Wm  = (const float*)d_in[13];
    const float* bm  = (const float*)d_in[14];
    float* outp = (float*)d_out;

    float* base = nullptr;
    cudaGetSymbolAddress((void**)&base, g_scratch);
    float* q    = base;
    float* k    = base + N_BSE;
    float* vv   = base + 2*N_BSE;
    float* attn = base + 3*N_BSE;
    float* mixd = base + 4*N_BSE;
    float* qlat = base + 5*N_BSE;
    float* klat = base + 5*N_BSE + N_LAT;

    __nv_bfloat16* abf = nullptr;
    cudaGetSymbolAddress((void**)&abf, g_abf);
    __nv_bfloat16* wbf = nullptr;
    cudaGetSymbolAddress((void**)&wbf, g_wbf);
    __nv_bfloat16* wqb = wbf;
    __nv_bfloat16* wkb = wbf + (size_t)2048 * GK;
    __nv_bfloat16* wvb = wbf + (size_t)2 * 2048 * GK;
    __nv_bfloat16* wob = wbf + (size_t)3 * 2048 * GK;

    cudaFuncSetAttribute(gemm_mma,
        cudaFuncAttributeMaxDynamicSharedMemorySize, GEMM_SMEM);
    cudaFuncSetAttribute(attention_kernel,
        cudaFuncAttributeMaxDynamicSharedMemorySize, ATT_SMEM_BYTES);
    cudaFuncSetAttribute(mixer_kernel,
        cudaFuncAttributeMaxDynamicSharedMemorySize, MIX_SMEM_BYTES);

    dim3 cwg(64, 64);
    conv_a<<<MM * 2048 / 1024, 256>>>(x, abf);
    conv_w<<<cwg, 256>>>(Wq, wqb);
    conv_w<<<cwg, 256>>>(Wk, wkb);
    conv_w<<<cwg, 256>>>(Wv, wvb);
    conv_w<<<cwg, 256>>>(Wo, wob);

    dim3 gg(2048 / 128, MM / 128);   // (16, 32)
    gemm_mma<<<gg, 256, GEMM_SMEM>>>(abf, wqb, bq,  q);
    gemm_mma<<<gg, 256, GEMM_SMEM>>>(abf, wkb, bk_, k);
    gemm_mma<<<gg, 256, GEMM_SMEM>>>(abf, wvb, bv_, vv);

    latent_kernel<<<BB*SS, 256>>>(q, Wql, bql, qlat);
    latent_kernel<<<BB*SS, 256>>>(k, Wkl, bkl, klat);

    attention_kernel<<<dim3(SS/64, HH, BB), 256, ATT_SMEM_BYTES>>>(qlat, klat, vv, attn);

    mixer_kernel<<<(BB*HH*SS)/16, 256, MIX_SMEM_BYTES>>>(attn, Wm, bm, mixd);

    conv_a<<<MM * 2048 / 1024, 256>>>(mixd, abf);
    gemm_mma<<<gg, 256, GEMM_SMEM>>>(abf, wob, bo, outp);
}

// round 4
// speedup vs baseline: 1.4409x; 1.0001x over previous
#include <cuda_runtime.h>
#include <cuda_bf16.h>
#include <math.h>
#include <stdint.h>

// Problem constants
#define BB  2
#define SS  2048
#define EE  2048
#define HH  16
#define DHH 128
#define LL  64
#define MM  (BB*SS)          // 4096 rows for the big GEMMs

#define N_BSE ((size_t)BB*SS*EE)       // 8388608
#define N_LAT ((size_t)BB*HH*SS*LL)    // 4194304

// fp32 scratch: q, k, v, attn_out, mixed (5x N_BSE) + q_lat, k_lat (2x N_LAT)
__device__ float g_scratch[5*8388608 + 2*4194304];
// bf16 split-stacked operands: A' [4096, 6144], 4x W'^T [2048, 6144]
__device__ __nv_bfloat16 g_abf[(size_t)4096 * 6144];
__device__ __nv_bfloat16 g_wbf[4][(size_t)2048 * 6144];

// ===========================================================================
// Helpers
// ===========================================================================
__device__ __forceinline__ uint32_t smem_u32(const void* p) {
    uint32_t a;
    asm("{ .reg .u64 t; cvta.to.shared.u64 t, %1; cvt.u32.u64 %0, t; }"
        : "=r"(a) : "l"(p));
    return a;
}

#define CP_ASYNC16(sm, gp) \
    asm volatile("cp.async.cg.shared.global [%0], [%1], 16;" \
        :: "r"((uint32_t)(sm)), "l"(gp) : "memory")
#define CP_COMMIT() asm volatile("cp.async.commit_group;" ::: "memory")
#define CP_WAIT(n)  asm volatile("cp.async.wait_group %0;" :: "n"(n) : "memory")

// SW64 swizzle for 64-byte rows (8-row atom), conflict-free for 16B accesses
#define SWZ64(o) ((o) ^ (((o) >> 3) & 0x30))

#define LDMATRIX_X4(r0, r1, r2, r3, addr) \
    asm volatile("ldmatrix.sync.aligned.m8n8.x4.shared.b16 {%0,%1,%2,%3}, [%4];" \
        : "=r"(r0), "=r"(r1), "=r"(r2), "=r"(r3) : "r"(addr))

#define MMA_BF16(c, a, b) \
    asm volatile("mma.sync.aligned.m16n8k16.row.col.f32.bf16.bf16.f32 " \
        "{%0,%1,%2,%3}, {%4,%5,%6,%7}, {%8,%9}, {%0,%1,%2,%3};" \
        : "+f"((c)[0]), "+f"((c)[1]), "+f"((c)[2]), "+f"((c)[3]) \
        : "r"((a)[0]), "r"((a)[1]), "r"((a)[2]), "r"((a)[3]), \
          "r"((b)[0]), "r"((b)[1]))

// ===========================================================================
// Conversion kernels: fp32 -> bf16 hi/lo, split-stacked along K' = 6144
// ===========================================================================
#define GK  6144
#define GKB (GK * 2)   // row stride in bytes

// A' [M, 6144]: cols [0:2048)=hi, [2048:4096)=hi, [4096:6144)=lo
__global__ __launch_bounds__(256)
void conv_a(const float* __restrict__ in, __nv_bfloat16* __restrict__ out) {
    int i4 = (blockIdx.x * 256 + threadIdx.x) * 4;
    int m = i4 >> 11, k = i4 & 2047;
    float4 xv = *(const float4*)(in + (size_t)m * 2048 + k);
    __nv_bfloat16 h[4], l[4];
    float xs[4] = {xv.x, xv.y, xv.z, xv.w};
#pragma unroll
    for (int j = 0; j < 4; j++) {
        h[j] = __float2bfloat16(xs[j]);
        l[j] = __float2bfloat16(xs[j] - __bfloat162float(h[j]));
    }
    size_t base = (size_t)m * GK + k;
    __nv_bfloat162 h01, h23, l01, l23;
    h01.x = h[0]; h01.y = h[1]; h23.x = h[2]; h23.y = h[3];
    l01.x = l[0]; l01.y = l[1]; l23.x = l[2]; l23.y = l[3];
    *(__nv_bfloat162*)(out + base)            = h01;
    *(__nv_bfloat162*)(out + base + 2)        = h23;
    *(__nv_bfloat162*)(out + base + 2048)     = h01;
    *(__nv_bfloat162*)(out + base + 2050)     = h23;
    *(__nv_bfloat162*)(out + base + 4096)     = l01;
    *(__nv_bfloat162*)(out + base + 4098)     = l23;
}

// W [K=2048, N=2048] -> W'^T [N rows, 6144]: cols [0:2048)=hi, [2048:4096)=lo, [4096:6144)=hi
__global__ __launch_bounds__(256)
void conv_w(const float* __restrict__ W, __nv_bfloat16* __restrict__ out) {
    __shared__ float ts[32][33];
    const int tid = threadIdx.x;
    const int tx = tid & 31, ty = tid >> 5;      // ty 0..7
    const int n0 = blockIdx.x * 32, k0 = blockIdx.y * 32;
#pragma unroll
    for (int it = 0; it < 4; it++)
        ts[ty + it*8][tx] = W[(size_t)(k0 + ty + it*8) * 2048 + n0 + tx];
    __syncthreads();
#pragma unroll
    for (int it = 0; it < 4; it++) {
        int r = ty + it*8;                        // output row n = n0 + r
        float v = ts[tx][r];                      // W[k0+tx, n0+r]
        __nv_bfloat16 hi = __float2bfloat16(v);
        __nv_bfloat16 lo = __float2bfloat16(v - __bfloat162float(hi));
        size_t ob = (size_t)(n0 + r) * GK + k0 + tx;
        out[ob]        = hi;
        out[ob + 2048] = lo;
        out[ob + 4096] = hi;
    }
}

// ===========================================================================
// mma.sync bf16 GEMM: C[4096,2048] = A'[4096,6144] @ W'^T[2048,6144]^T + bias
// 128x128 tile, BK=32, 8 warps (2x4), 4-stage cp.async pipeline, SW64 smem.
// ===========================================================================
#define KITERS   192                       // 6144 / 32
#define STAGE_A  8192                      // 128 rows * 64B
#define STAGE_B  8192
#define B_OFF    (4 * STAGE_A)             // 32768
#define GEMM_SMEM (B_OFF + 4 * STAGE_B)    // 65536

__global__ __launch_bounds__(256, 2)
void gemm_mma(const __nv_bfloat16* __restrict__ A, const __nv_bfloat16* __restrict__ Bt,
              const float* __restrict__ bias, float* __restrict__ C) {
    extern __shared__ char gsm[];
    uint32_t sb = smem_u32(gsm);
    const int tid = threadIdx.x;
    const int wid = tid >> 5, lane = tid & 31;
    const int m0 = blockIdx.y * 128, n0 = blockIdx.x * 128;
    const int wm0 = (wid >> 2) * 64;       // warp m offset in tile
    const int wn0 = (wid & 3) * 32;        // warp n offset in tile

    const char* Ab = (const char*)A + (size_t)m0 * GKB;
    const char* Bb = (const char*)Bt + (size_t)n0 * GKB;

    // per-thread load slots: 2 x 16B for A, 2 x 16B for B per chunk
    const int lr = tid >> 2;               // 0..63 base row
    const int lq = tid & 3;                // quad

    auto load_chunk = [&](int j) {
        const int st = j & 3;
        uint32_t ab = sb + st * STAGE_A;
        uint32_t bb = sb + B_OFF + st * STAGE_B;
        const char* ag = Ab + (size_t)j * 64;
        const char* bg = Bb + (size_t)j * 64;
#pragma unroll
        for (int i = 0; i < 2; i++) {
            int r = lr + i * 64;
            CP_ASYNC16(ab + SWZ64(r * 64 + lq * 16), ag + (size_t)r * GKB + lq * 16);
        }
#pragma unroll
        for (int i = 0; i < 2; i++) {
            int r = lr + i * 64;
            CP_ASYNC16(bb + SWZ64(r * 64 + lq * 16), bg + (size_t)r * GKB + lq * 16);
        }
        CP_COMMIT();
    };

    float acc[4][4][4];
#pragma unroll
    for (int mt = 0; mt < 4; mt++)
#pragma unroll
        for (int nt = 0; nt < 4; nt++)
#pragma unroll
            for (int e = 0; e < 4; e++) acc[mt][nt][e] = 0.f;

    // prologue: stages 0..2
    load_chunk(0);
    load_chunk(1);
    load_chunk(2);

    const int arow = lane & 15;            // ldmatrix row within 16
    const int acol = (lane >> 4) * 16;     // ldmatrix 8-col group (bytes)

    for (int it = 0; it < KITERS; it++) {
        CP_WAIT(2);
        __syncthreads();

        // prefetch next chunk (empty commit keeps group counting uniform)
        if (it + 3 < KITERS) load_chunk(it + 3);
        else                 CP_COMMIT();

        const int st = it & 3;
        uint32_t ab = sb + st * STAGE_A;
        uint32_t bb = sb + B_OFF + st * STAGE_B;

#pragma unroll
        for (int kk = 0; kk < 2; kk++) {
            uint32_t a[4][4];
            uint32_t b[4][2];
#pragma unroll
            for (int mt = 0; mt < 4; mt++) {
                uint32_t addr = ab + SWZ64((wm0 + mt*16 + arow) * 64 + kk*32 + acol);
                LDMATRIX_X4(a[mt][0], a[mt][1], a[mt][2], a[mt][3], addr);
            }
#pragma unroll
            for (int nb = 0; nb < 2; nb++) {
                uint32_t r0, r1, r2, r3;
                uint32_t addr = bb + SWZ64((wn0 + nb*16 + arow) * 64 + kk*32 + acol);
                LDMATRIX_X4(r0, r1, r2, r3, addr);
                b[nb*2+0][0] = r0; b[nb*2+0][1] = r2;
                b[nb*2+1][0] = r1; b[nb*2+1][1] = r3;
            }
#pragma unroll
            for (int mt = 0; mt < 4; mt++)
#pragma unroll
                for (int nt = 0; nt < 4; nt++)
                    MMA_BF16(acc[mt][nt], a[mt], b[nt]);
        }
        __syncthreads();
    }

    // Epilogue: c-frag mapping: rows (lane>>2)+{0,8}, cols (lane&3)*2+{0,1}
    const int er = lane >> 2, ec = (lane & 3) * 2;
#pragma unroll
    for (int mt = 0; mt < 4; mt++) {
#pragma unroll
        for (int nt = 0; nt < 4; nt++) {
            int col = n0 + wn0 + nt*8 + ec;
            float b0 = bias[col], b1 = bias[col + 1];
            int row0 = m0 + wm0 + mt*16 + er;
            float2 o0, o1;
            o0.x = acc[mt][nt][0] + b0; o0.y = acc[mt][nt][1] + b1;
            o1.x = acc[mt][nt][2] + b0; o1.y = acc[mt][nt][3] + b1;
            *(float2*)(C + (size_t)row0 * 2048 + col)       = o0;
            *(float2*)(C + (size_t)(row0 + 8) * 2048 + col) = o1;
        }
    }
}

// ---------------------------------------------------------------------------
// Latent projection + elu+1 (unchanged from R1)
// ---------------------------------------------------------------------------
__global__ __launch_bounds__(256)
void latent_kernel(const float* __restrict__ proj, const float* __restrict__ Wl,
                   const float* __restrict__ bl, float* __restrict__ lat) {
    __shared__ float w_s[DHH * LL];
    __shared__ float row_s[EE];
    __shared__ float b_s[LL];

    const int tid = threadIdx.x;
    const int bidx = blockIdx.x;
    const int b = bidx / SS, s = bidx % SS;

    for (int i = tid; i < DHH * LL; i += 256) w_s[i] = Wl[i];
    for (int i = tid; i < EE; i += 256)       row_s[i] = proj[(size_t)bidx * EE + i];
    if (tid < LL) b_s[tid] = bl[tid];
    __syncthreads();

    const int l = tid & 63;
    const int hb = tid >> 6;
#pragma unroll
    for (int i = 0; i < 4; i++) {
        const int h = hb * 4 + i;
        float acc = b_s[l];
        const float* rp = &row_s[h * DHH];
#pragma unroll 8
        for (int d = 0; d < DHH; d++) acc += rp[d] * w_s[d * LL + l];
        float r = (acc > 0.f) ? (acc + 1.f) : __expf(acc);
        lat[(((size_t)b * HH + h) * SS + s) * LL + l] = r;
    }
}

// ---------------------------------------------------------------------------
// Block attention (unchanged from R1)
// ---------------------------------------------------------------------------
#define ATT_SMEM_BYTES ((64*68 + 64*132 + 64*516 + 512 + 64) * 4)

__global__ __launch_bounds__(256, 1)
void attention_kernel(const float* __restrict__ qlat, const float* __restrict__ klat,
                      const float* __restrict__ v, float* __restrict__ outp) {
    extern __shared__ float sm[];
    float* q_s  = sm;
    float* kv_s = sm + 64*68;
    float* s_s  = kv_s + 64*132;
    float* red  = s_s + 64*516;
    float* linv = red + 512;

    const int tid = threadIdx.x;
    const int tx = tid & 15, ty = tid >> 4;
    const int qt = blockIdx.x, h = blockIdx.y, b = blockIdx.z;
    const int qr0 = qt * 64;

    const float* qb = qlat + ((size_t)(b*HH + h) * SS + qr0) * LL;
    const float* kb = klat + (size_t)(b*HH + h) * SS * LL;
    const float* vb = v + (size_t)b * SS * EE + h * DHH;

    {
        int r = tid >> 2, c = (tid & 3) * 16;
#pragma unroll
        for (int j = 0; j < 16; j += 4)
            *(float4*)&q_s[r*68 + c + j] = *(const float4*)(qb + (size_t)r*LL + c + j);
    }

    float out[4][8];
#pragma unroll
    for (int i = 0; i < 4; i++)
#pragma unroll
        for (int j = 0; j < 8; j++) out[i][j] = 0.f;

    const int r0 = ty * 4, c0 = tx * 8;

    for (int kvb = 0; kvb < 4; kvb++) {
        const int f00 = kvb * 512;

        for (int kc = 0; kc < 4; kc++) {
            __syncthreads();
            {
                int f = tid >> 1, l0 = (tid & 1) * 32;
                const float* kp = kb + (size_t)(f00 + kc*128 + f) * LL + l0;
#pragma unroll
                for (int j = 0; j < 32; j += 4) {
                    float4 t4 = *(const float4*)(kp + j);
                    kv_s[(l0+j+0)*132 + f] = t4.x;
                    kv_s[(l0+j+1)*132 + f] = t4.y;
                    kv_s[(l0+j+2)*132 + f] = t4.z;
                    kv_s[(l0+j+3)*132 + f] = t4.w;
                }
            }
            __syncthreads();
            float acc[4][8];
#pragma unroll
            for (int i = 0; i < 4; i++)
#pragma unroll
                for (int j = 0; j < 8; j++) acc[i][j] = 0.f;
#pragma unroll 8
            for (int l = 0; l < 64; l++) {
                float qv[4], kf[8];
#pragma unroll
                for (int i = 0; i < 4; i++) qv[i] = q_s[(r0+i)*68 + l];
                *(float4*)&kf[0] = *(const float4*)&kv_s[l*132 + c0];
                *(float4*)&kf[4] = *(const float4*)&kv_s[l*132 + c0 + 4];
#pragma unroll
                for (int i = 0; i < 4; i++)
#pragma unroll
                    for (int j = 0; j < 8; j++) acc[i][j] += qv[i] * kf[j];
            }
#pragma unroll
            for (int i = 0; i < 4; i++) {
                float* sp = &s_s[(r0+i)*516 + kc*128 + c0];
                float4 o0, o1;
                o0.x = acc[i][0]*0.125f; o0.y = acc[i][1]*0.125f;
                o0.z = acc[i][2]*0.125f; o0.w = acc[i][3]*0.125f;
                o1.x = acc[i][4]*0.125f; o1.y = acc[i][5]*0.125f;
                o1.z = acc[i][6]*0.125f; o1.w = acc[i][7]*0.125f;
                *(float4*)sp       = o0;
                *(float4*)(sp + 4) = o1;
            }
        }
        __syncthreads();

        {
            const int row = tid >> 2, seg = tid & 3;
            float* srow = &s_s[row*516 + seg*128];
            float mx = -3.0e38f;
            for (int i = 0; i < 128; i++) mx = fmaxf(mx, srow[i]);
            red[row*4 + seg] = mx;
            __syncthreads();
            float m = fmaxf(fmaxf(red[row*4+0], red[row*4+1]),
                            fmaxf(red[row*4+2], red[row*4+3]));
            float sumv = 0.f;
            for (int i = 0; i < 128; i++) {
                float e = __expf(srow[i] - m);
                srow[i] = e;
                sumv += e;
            }
            red[256 + row*4 + seg] = sumv;
            __syncthreads();
            if (seg == 0) {
                float ls = red[256+row*4] + red[256+row*4+1] +
                           red[256+row*4+2] + red[256+row*4+3];
                linv[row] = 1.0f / ls;
            }
        }
        __syncthreads();

        for (int vc = 0; vc < 8; vc++) {
            {
                int f = tid >> 2, d0 = (tid & 3) * 32;
                const float* vp = vb + (size_t)(f00 + vc*64 + f) * EE + d0;
#pragma unroll
                for (int j = 0; j < 32; j += 4)
                    *(float4*)&kv_s[f*132 + d0 + j] = *(const float4*)(vp + j);
            }
            __syncthreads();
            float lv[4];
#pragma unroll
            for (int i = 0; i < 4; i++) lv[i] = linv[r0 + i];
#pragma unroll 8
            for (int f = 0; f < 64; f++) {
                float pv[4], vf[8];
#pragma unroll
                for (int i = 0; i < 4; i++)
                    pv[i] = s_s[(r0+i)*516 + vc*64 + f] * lv[i];
                *(float4*)&vf[0] = *(const float4*)&kv_s[f*132 + c0];
                *(float4*)&vf[4] = *(const float4*)&kv_s[f*132 + c0 + 4];
#pragma unroll
                for (int i = 0; i < 4; i++)
#pragma unroll
                    for (int j = 0; j < 8; j++) out[i][j] += pv[i] * vf[j];
            }
            __syncthreads();
        }
    }

    float* op = outp + ((size_t)(b*HH + h) * SS + qr0) * DHH;
#pragma unroll
    for (int i = 0; i < 4; i++) {
        float4 o0, o1;
        o0.x = out[i][0]; o0.y = out[i][1]; o0.z = out[i][2]; o0.w = out[i][3];
        o1.x = out[i][4]; o1.y = out[i][5]; o1.z = out[i][6]; o1.w = out[i][7];
        *(float4*)&op[(r0+i)*DHH + c0]     = o0;
        *(float4*)&op[(r0+i)*DHH + c0 + 4] = o1;
    }
}

// ---------------------------------------------------------------------------
// Mixer (unchanged from R1)
// ---------------------------------------------------------------------------
#define MIX_SMEM_BYTES ((128*130 + 16*128) * 4)

__device__ __forceinline__ float gelu_tanh(float x) {
    float x3 = x * x * x;
    return 0.5f * x * (1.f + tanhf(0.7978845608028654f * (x + 0.044715f * x3)));
}

__global__ __launch_bounds__(256)
void mixer_kernel(const float* __restrict__ attn, const float* __restrict__ Wm,
                  const float* __restrict__ bm, float* __restrict__ mixed) {
    extern __shared__ float sm[];
    float* wm_s = sm;
    float* in_s = sm + 128*130;

    const int tid = threadIdx.x;
    const int R0 = blockIdx.x * 16;

    for (int i = tid; i < DHH*DHH; i += 256) {
        int d = i >> 7, c = i & 127;
        wm_s[d*130 + c] = Wm[i];
    }
    for (int i = tid; i < 16*DHH; i += 256)
        in_s[i] = attn[(size_t)R0 * DHH + i];
    __syncthreads();

    const int cp = (tid & 63) * 2;
    const int rg = tid >> 6;

    float acc[4][2];
#pragma unroll
    for (int i = 0; i < 4; i++) { acc[i][0] = 0.f; acc[i][1] = 0.f; }

#pragma unroll 8
    for (int d = 0; d < 128; d++) {
        float w0 = wm_s[d*130 + cp], w1 = wm_s[d*130 + cp + 1];
#pragma unroll
        for (int i = 0; i < 4; i++) {
            float a = in_s[(rg*4 + i)*128 + d];
            acc[i][0] += a * w0;
            acc[i][1] += a * w1;
        }
    }

    float b0 = bm[cp], b1 = bm[cp + 1];
#pragma unroll
    for (int i = 0; i < 4; i++) {
        int R = R0 + rg*4 + i;
        int b = R / (HH*SS);
        int rem = R % (HH*SS);
        int h = rem / SS, s = rem % SS;
        float2 o;
        o.x = gelu_tanh(acc[i][0] + b0);
        o.y = gelu_tanh(acc[i][1] + b1);
        *(float2*)&mixed[((size_t)b*SS + s)*EE + h*DHH + cp] = o;
    }
}

// ---------------------------------------------------------------------------
// Launch
// ---------------------------------------------------------------------------
extern "C" void kernel_launch(void* const* d_in, const int* in_sizes, int n_in,
                              void* d_out, int out_size) {
    const float* x   = (const float*)d_in[0];
    const float* Wq  = (const float*)d_in[1];
    const float* bq  = (const float*)d_in[2];
    const float* Wk  = (const float*)d_in[3];
    const float* bk_ = (const float*)d_in[4];
    const float* Wv  = (const float*)d_in[5];
    const float* bv_ = (const float*)d_in[6];
    const float* Wo  = (const float*)d_in[7];
    const float* bo  = (const float*)d_in[8];
    const float* Wql = (const float*)d_in[9];
    const float* bql = (const float*)d_in[10];
    const float* Wkl = (const float*)d_in[11];
    const float* bkl = (const float*)d_in[12];
    const float* Wm  = (const float*)d_in[13];
    const float* bm  = (const float*)d_in[14];
    float* outp = (float*)d_out;

    float* base = nullptr;
    cudaGetSymbolAddress((void**)&base, g_scratch);
    float* q    = base;
    float* k    = base + N_BSE;
    float* vv   = base + 2*N_BSE;
    float* attn = base + 3*N_BSE;
    float* mixd = base + 4*N_BSE;
    float* qlat = base + 5*N_BSE;
    float* klat = base + 5*N_BSE + N_LAT;

    __nv_bfloat16* abf = nullptr;
    cudaGetSymbolAddress((void**)&abf, g_abf);
    __nv_bfloat16* wbf = nullptr;
    cudaGetSymbolAddress((void**)&wbf, g_wbf);
    __nv_bfloat16* wqb = wbf;
    __nv_bfloat16* wkb = wbf + (size_t)2048 * GK;
    __nv_bfloat16* wvb = wbf + (size_t)2 * 2048 * GK;
    __nv_bfloat16* wob = wbf + (size_t)3 * 2048 * GK;

    cudaFuncSetAttribute(gemm_mma,
        cudaFuncAttributeMaxDynamicSharedMemorySize, GEMM_SMEM);
    cudaFuncSetAttribute(attention_kernel,
        cudaFuncAttributeMaxDynamicSharedMemorySize, ATT_SMEM_BYTES);
    cudaFuncSetAttribute(mixer_kernel,
        cudaFuncAttributeMaxDynamicSharedMemorySize, MIX_SMEM_BYTES);

    dim3 cwg(64, 64);
    conv_a<<<MM * 2048 / 1024, 256>>>(x, abf);
    conv_w<<<cwg, 256>>>(Wq, wqb);
    conv_w<<<cwg, 256>>>(Wk, wkb);
    conv_w<<<cwg, 256>>>(Wv, wvb);
    conv_w<<<cwg, 256>>>(Wo, wob);

    dim3 gg(2048 / 128, MM / 128);   // (16, 32)
    gemm_mma<<<gg, 256, GEMM_SMEM>>>(abf, wqb, bq,  q);
    gemm_mma<<<gg, 256, GEMM_SMEM>>>(abf, wkb, bk_, k);
    gemm_mma<<<gg, 256, GEMM_SMEM>>>(abf, wvb, bv_, vv);

    latent_kernel<<<BB*SS, 256>>>(q, Wql, bql, qlat);
    latent_kernel<<<BB*SS, 256>>>(k, Wkl, bkl, klat);

    attention_kernel<<<dim3(SS/64, HH, BB), 256, ATT_SMEM_BYTES>>>(qlat, klat, vv, attn);

    mixer_kernel<<<(BB*HH*SS)/16, 256, MIX_SMEM_BYTES>>>(attn, Wm, bm, mixd);

    conv_a<<<MM * 2048 / 1024, 256>>>(mixd, abf);
    gemm_mma<<<gg, 256, GEMM_SMEM>>>(abf, wob, bo, outp);
}

// round 6
// speedup vs baseline: 2.6801x; 1.8601x over previous
#include <cuda_runtime.h>
#include <cuda_bf16.h>
#include <math.h>
#include <stdint.h>

// Problem constants
#define BB  2
#define SS  2048
#define EE  2048
#define HH  16
#define DHH 128
#define LL  64
#define MM  (BB*SS)          // 4096 rows for the big GEMMs

#define N_BSE ((size_t)BB*SS*EE)       // 8388608
#define N_LAT ((size_t)BB*HH*SS*LL)    // 4194304

// fp32 scratch: q, k, v, attn_out, mixed (5x N_BSE)
__device__ float g_scratch[5*8388608];
// bf16 split-stacked operands: A' [4096, 6144], 4x W'^T [2048, 6144]
__device__ __nv_bfloat16 g_abf[(size_t)4096 * 6144];
__device__ __nv_bfloat16 g_wbf[4][(size_t)2048 * 6144];
// attention operands: qh, ql, kh, kl planes [B,H,S,64]; vh, vl [B,H,S,128]
__device__ __nv_bfloat16 g_qk[4 * 4194304];
__device__ __nv_bfloat16 g_v[2 * 8388608];

// ===========================================================================
// Helpers
// ===========================================================================
__device__ __forceinline__ uint32_t smem_u32(const void* p) {
    uint32_t a;
    asm("{ .reg .u64 t; cvta.to.shared.u64 t, %1; cvt.u32.u64 %0, t; }"
        : "=r"(a) : "l"(p));
    return a;
}

#define CP_ASYNC16(sm, gp) \
    asm volatile("cp.async.cg.shared.global [%0], [%1], 16;" \
        :: "r"((uint32_t)(sm)), "l"(gp) : "memory")
#define CP_COMMIT() asm volatile("cp.async.commit_group;" ::: "memory")
#define CP_WAIT(n)  asm volatile("cp.async.wait_group %0;" :: "n"(n) : "memory")

// swizzles: 64B rows, 128B rows, 256B rows
#define SWZ64(o)  ((o) ^ (((o) >> 3) & 0x30))
#define SW128(o)  ((o) ^ (((o) >> 3) & 0x70))
#define SW256(o)  ((o) ^ (((o) >> 4) & 0x70))

#define LDMATRIX_X4(r0, r1, r2, r3, addr) \
    asm volatile("ldmatrix.sync.aligned.m8n8.x4.shared.b16 {%0,%1,%2,%3}, [%4];" \
        : "=r"(r0), "=r"(r1), "=r"(r2), "=r"(r3) : "r"(addr))

#define LDMATRIX_X4_T(r0, r1, r2, r3, addr) \
    asm volatile("ldmatrix.sync.aligned.m8n8.x4.trans.shared.b16 {%0,%1,%2,%3}, [%4];" \
        : "=r"(r0), "=r"(r1), "=r"(r2), "=r"(r3) : "r"(addr))

#define MMA_BF16(c, a, b) \
    asm volatile("mma.sync.aligned.m16n8k16.row.col.f32.bf16.bf16.f32 " \
        "{%0,%1,%2,%3}, {%4,%5,%6,%7}, {%8,%9}, {%0,%1,%2,%3};" \
        : "+f"((c)[0]), "+f"((c)[1]), "+f"((c)[2]), "+f"((c)[3]) \
        : "r"((a)[0]), "r"((a)[1]), "r"((a)[2]), "r"((a)[3]), \
          "r"((b)[0]), "r"((b)[1]))

#define MMA_BF16S(c, a, b0, b1) \
    asm volatile("mma.sync.aligned.m16n8k16.row.col.f32.bf16.bf16.f32 " \
        "{%0,%1,%2,%3}, {%4,%5,%6,%7}, {%8,%9}, {%0,%1,%2,%3};" \
        : "+f"((c)[0]), "+f"((c)[1]), "+f"((c)[2]), "+f"((c)[3]) \
        : "r"((a)[0]), "r"((a)[1]), "r"((a)[2]), "r"((a)[3]), \
          "r"(b0), "r"(b1))

__device__ __forceinline__ uint32_t pack_bf16(float lo, float hi) {
    uint32_t r;
    asm("cvt.rn.bf16x2.f32 %0, %1, %2;" : "=r"(r) : "f"(hi), "f"(lo));
    return r;
}

// ===========================================================================
// Conversion kernels: fp32 -> bf16 hi/lo, split-stacked along K' = 6144
// ===========================================================================
#define GK  6144
#define GKB (GK * 2)   // row stride in bytes

// A' [M, 6144]: cols [0:2048)=hi, [2048:4096)=hi, [4096:6144)=lo
__global__ __launch_bounds__(256)
void conv_a(const float* __restrict__ in, __nv_bfloat16* __restrict__ out) {
    int i4 = (blockIdx.x * 256 + threadIdx.x) * 4;
    int m = i4 >> 11, k = i4 & 2047;
    float4 xv = *(const float4*)(in + (size_t)m * 2048 + k);
    __nv_bfloat16 h[4], l[4];
    float xs[4] = {xv.x, xv.y, xv.z, xv.w};
#pragma unroll
    for (int j = 0; j < 4; j++) {
        h[j] = __float2bfloat16(xs[j]);
        l[j] = __float2bfloat16(xs[j] - __bfloat162float(h[j]));
    }
    size_t base = (size_t)m * GK + k;
    __nv_bfloat162 h01, h23, l01, l23;
    h01.x = h[0]; h01.y = h[1]; h23.x = h[2]; h23.y = h[3];
    l01.x = l[0]; l01.y = l[1]; l23.x = l[2]; l23.y = l[3];
    *(__nv_bfloat162*)(out + base)            = h01;
    *(__nv_bfloat162*)(out + base + 2)        = h23;
    *(__nv_bfloat162*)(out + base + 2048)     = h01;
    *(__nv_bfloat162*)(out + base + 2050)     = h23;
    *(__nv_bfloat162*)(out + base + 4096)     = l01;
    *(__nv_bfloat162*)(out + base + 4098)     = l23;
}

// W [K=2048, N=2048] -> W'^T [N rows, 6144]: cols [0:2048)=hi, [2048:4096)=lo, [4096:6144)=hi
__global__ __launch_bounds__(256)
void conv_w(const float* __restrict__ W, __nv_bfloat16* __restrict__ out) {
    __shared__ float ts[32][33];
    const int tid = threadIdx.x;
    const int tx = tid & 31, ty = tid >> 5;      // ty 0..7
    const int n0 = blockIdx.x * 32, k0 = blockIdx.y * 32;
#pragma unroll
    for (int it = 0; it < 4; it++)
        ts[ty + it*8][tx] = W[(size_t)(k0 + ty + it*8) * 2048 + n0 + tx];
    __syncthreads();
#pragma unroll
    for (int it = 0; it < 4; it++) {
        int r = ty + it*8;                        // output row n = n0 + r
        float v = ts[tx][r];                      // W[k0+tx, n0+r]
        __nv_bfloat16 hi = __float2bfloat16(v);
        __nv_bfloat16 lo = __float2bfloat16(v - __bfloat162float(hi));
        size_t ob = (size_t)(n0 + r) * GK + k0 + tx;
        out[ob]        = hi;
        out[ob + 2048] = lo;
        out[ob + 4096] = hi;
    }
}

// V [B,S,E] fp32 -> vh/vl [B,H,S,DH] bf16   (grid must be N_BSE/1024 = 8192)
__global__ __launch_bounds__(256)
void conv_v(const float* __restrict__ vv, __nv_bfloat16* __restrict__ vh,
            __nv_bfloat16* __restrict__ vl) {
    size_t i4 = ((size_t)blockIdx.x * 256 + threadIdx.x) * 4;
    int d = (int)(i4 & 127);
    size_t r = i4 >> 7;              // (b*H + h)*S + s
    int s = (int)(r & 2047);
    size_t bh = r >> 11;
    int h = (int)(bh & 15), b = (int)(bh >> 4);
    const float* src = vv + ((size_t)b * SS + s) * EE + h * DHH + d;
    float4 x = *(const float4*)src;
    float xs[4] = {x.x, x.y, x.z, x.w};
    __nv_bfloat16 hi[4];
    float lo[4];
#pragma unroll
    for (int j = 0; j < 4; j++) {
        hi[j] = __float2bfloat16(xs[j]);
        lo[j] = xs[j] - __bfloat162float(hi[j]);
    }
    __nv_bfloat162 h01, h23, l01, l23;
    h01.x = hi[0]; h01.y = hi[1]; h23.x = hi[2]; h23.y = hi[3];
    l01.x = __float2bfloat16(lo[0]); l01.y = __float2bfloat16(lo[1]);
    l23.x = __float2bfloat16(lo[2]); l23.y = __float2bfloat16(lo[3]);
    *(__nv_bfloat162*)(vh + i4)     = h01;
    *(__nv_bfloat162*)(vh + i4 + 2) = h23;
    *(__nv_bfloat162*)(vl + i4)     = l01;
    *(__nv_bfloat162*)(vl + i4 + 2) = l23;
}

// ===========================================================================
// mma.sync bf16 GEMM (unchanged from R4)
// ===========================================================================
#define KITERS   192
#define STAGE_A  8192
#define STAGE_B  8192
#define B_OFF    (4 * STAGE_A)
#define GEMM_SMEM (B_OFF + 4 * STAGE_B)

__global__ __launch_bounds__(256, 2)
void gemm_mma(const __nv_bfloat16* __restrict__ A, const __nv_bfloat16* __restrict__ Bt,
              const float* __restrict__ bias, float* __restrict__ C) {
    extern __shared__ char gsm[];
    uint32_t sb = smem_u32(gsm);
    const int tid = threadIdx.x;
    const int wid = tid >> 5, lane = tid & 31;
    const int m0 = blockIdx.y * 128, n0 = blockIdx.x * 128;
    const int wm0 = (wid >> 2) * 64;
    const int wn0 = (wid & 3) * 32;

    const char* Ab = (const char*)A + (size_t)m0 * GKB;
    const char* Bb = (const char*)Bt + (size_t)n0 * GKB;

    const int lr = tid >> 2;
    const int lq = tid & 3;

    auto load_chunk = [&](int j) {
        const int st = j & 3;
        uint32_t ab = sb + st * STAGE_A;
        uint32_t bb = sb + B_OFF + st * STAGE_B;
        const char* ag = Ab + (size_t)j * 64;
        const char* bg = Bb + (size_t)j * 64;
#pragma unroll
        for (int i = 0; i < 2; i++) {
            int r = lr + i * 64;
            CP_ASYNC16(ab + SWZ64(r * 64 + lq * 16), ag + (size_t)r * GKB + lq * 16);
        }
#pragma unroll
        for (int i = 0; i < 2; i++) {
            int r = lr + i * 64;
            CP_ASYNC16(bb + SWZ64(r * 64 + lq * 16), bg + (size_t)r * GKB + lq * 16);
        }
        CP_COMMIT();
    };

    float acc[4][4][4];
#pragma unroll
    for (int mt = 0; mt < 4; mt++)
#pragma unroll
        for (int nt = 0; nt < 4; nt++)
#pragma unroll
            for (int e = 0; e < 4; e++) acc[mt][nt][e] = 0.f;

    load_chunk(0);
    load_chunk(1);
    load_chunk(2);

    const int arow = lane & 15;
    const int acol = (lane >> 4) * 16;

    for (int it = 0; it < KITERS; it++) {
        CP_WAIT(2);
        __syncthreads();

        if (it + 3 < KITERS) load_chunk(it + 3);
        else                 CP_COMMIT();

        const int st = it & 3;
        uint32_t ab = sb + st * STAGE_A;
        uint32_t bb = sb + B_OFF + st * STAGE_B;

#pragma unroll
        for (int kk = 0; kk < 2; kk++) {
            uint32_t a[4][4];
            uint32_t b[4][2];
#pragma unroll
            for (int mt = 0; mt < 4; mt++) {
                uint32_t addr = ab + SWZ64((wm0 + mt*16 + arow) * 64 + kk*32 + acol);
                LDMATRIX_X4(a[mt][0], a[mt][1], a[mt][2], a[mt][3], addr);
            }
#pragma unroll
            for (int nb = 0; nb < 2; nb++) {
                uint32_t r0, r1, r2, r3;
                uint32_t addr = bb + SWZ64((wn0 + nb*16 + arow) * 64 + kk*32 + acol);
                LDMATRIX_X4(r0, r1, r2, r3, addr);
                b[nb*2+0][0] = r0; b[nb*2+0][1] = r2;
                b[nb*2+1][0] = r1; b[nb*2+1][1] = r3;
            }
#pragma unroll
            for (int mt = 0; mt < 4; mt++)
#pragma unroll
                for (int nt = 0; nt < 4; nt++)
                    MMA_BF16(acc[mt][nt], a[mt], b[nt]);
        }
        __syncthreads();
    }

    const int er = lane >> 2, ec = (lane & 3) * 2;
#pragma unroll
    for (int mt = 0; mt < 4; mt++) {
#pragma unroll
        for (int nt = 0; nt < 4; nt++) {
            int col = n0 + wn0 + nt*8 + ec;
            float b0 = bias[col], b1 = bias[col + 1];
            int row0 = m0 + wm0 + mt*16 + er;
            float2 o0, o1;
            o0.x = acc[mt][nt][0] + b0; o0.y = acc[mt][nt][1] + b1;
            o1.x = acc[mt][nt][2] + b0; o1.y = acc[mt][nt][3] + b1;
            *(float2*)(C + (size_t)row0 * 2048 + col)       = o0;
            *(float2*)(C + (size_t)(row0 + 8) * 2048 + col) = o1;
        }
    }
}

// ===========================================================================
// Latent projection + elu+1 -> bf16 hi/lo planes [B,H,S,64]
// ===========================================================================
__global__ __launch_bounds__(256)
void latent_split(const float* __restrict__ proj, const float* __restrict__ Wl,
                  const float* __restrict__ bl, __nv_bfloat16* __restrict__ outh,
                  __nv_bfloat16* __restrict__ outl, float scale) {
    __shared__ float w_s[DHH * LL];   // [d][l] d-major, 32KB
    __shared__ float row_s[EE];       // 8KB
    __shared__ float b_s[LL];

    const int tid = threadIdx.x;
    const int bidx = blockIdx.x;          // b*S + s
    const int b = bidx >> 11, s = bidx & 2047;

    for (int i = tid; i < DHH * LL; i += 256) w_s[i] = Wl[i];
    for (int i = tid; i < EE; i += 256)       row_s[i] = proj[(size_t)bidx * EE + i];
    if (tid < LL) b_s[tid] = bl[tid];
    __syncthreads();

    const int l2 = (tid & 31) * 2;
    const int hg = tid >> 5;              // warp id = head group
#pragma unroll
    for (int hh = 0; hh < 2; hh++) {
        const int h = hg * 2 + hh;
        const float* rp = &row_s[h * DHH];
        float a0 = b_s[l2], a1 = b_s[l2 + 1];
#pragma unroll 4
        for (int d0 = 0; d0 < DHH; d0 += 4) {
            float4 r4 = *(const float4*)&rp[d0];
            const float* wp = &w_s[d0 * LL + l2];
            float2 w0 = *(const float2*)(wp);
            float2 w1 = *(const float2*)(wp + LL);
            float2 w2 = *(const float2*)(wp + 2*LL);
            float2 w3 = *(const float2*)(wp + 3*LL);
            a0 += r4.x*w0.x + r4.y*w1.x + r4.z*w2.x + r4.w*w3.x;
            a1 += r4.x*w0.y + r4.y*w1.y + r4.z*w2.y + r4.w*w3.y;
        }
        float r0 = ((a0 > 0.f) ? (a0 + 1.f) : __expf(a0)) * scale;
        float r1 = ((a1 > 0.f) ? (a1 + 1.f) : __expf(a1)) * scale;
        __nv_bfloat162 hi2, lo2;
        hi2.x = __float2bfloat16(r0);
        hi2.y = __float2bfloat16(r1);
        lo2.x = __float2bfloat16(r0 - __bfloat162float(hi2.x));
        lo2.y = __float2bfloat16(r1 - __bfloat162float(hi2.y));
        size_t ob = (((size_t)(b * HH + h)) * SS + s) * LL + l2;
        *(__nv_bfloat162*)(outh + ob) = hi2;
        *(__nv_bfloat162*)(outl + ob) = lo2;
    }
}

// ===========================================================================
// Tensor-core block attention.
// grid (S/128, H, B); 256 threads (8 warps x m16).
// kv chunks of 64, per-512 exact softmax via exp(s-16) (no max pass),
// split-bf16 for both QK^T (qh*kh+qh*kl+ql*kh) and P@V (ph*vh+ph*vl+pl*vh).
// ===========================================================================
#define QH_OFF  0
#define QL_OFF  16384
#define KH_OFF  32768          // + st*8192
#define KL_OFF  49152          // + st*8192
#define VH_OFF  65536          // + st*16384
#define VL_OFF  98304          // + st*16384
#define ATT_SMEM 131072
#define NCHN    32             // 2048/64 kv chunks

__global__ __launch_bounds__(256, 1)
void attention_mma(const __nv_bfloat16* __restrict__ qh_g, const __nv_bfloat16* __restrict__ ql_g,
                   const __nv_bfloat16* __restrict__ kh_g, const __nv_bfloat16* __restrict__ kl_g,
                   const __nv_bfloat16* __restrict__ vh_g, const __nv_bfloat16* __restrict__ vl_g,
                   float* __restrict__ outp) {
    extern __shared__ char asmem[];
    uint32_t sb = smem_u32(asmem);
    const int tid = threadIdx.x, wid = tid >> 5, lane = tid & 31;
    const int qt = blockIdx.x, h = blockIdx.y, b = blockIdx.z;
    const int qr0 = qt * 128;
    const size_t bh = (size_t)(b * HH + h);

    const char* qhb = (const char*)(qh_g + (bh * SS + qr0) * LL);
    const char* qlb = (const char*)(ql_g + (bh * SS + qr0) * LL);
    const char* khb = (const char*)(kh_g + bh * SS * LL);
    const char* klb = (const char*)(kl_g + bh * SS * LL);
    const char* vhb = (const char*)(vh_g + bh * SS * DHH);
    const char* vlb = (const char*)(vl_g + bh * SS * DHH);

    // ---- q load (cp.async, part of group 0) ----
#pragma unroll
    for (int i = 0; i < 4; i++) {
        int e = tid + i * 256;
        int r = e >> 3, c = (e & 7) * 16;
        CP_ASYNC16(sb + QH_OFF + SW128(r * 128 + c), qhb + (size_t)r * 128 + c);
        CP_ASYNC16(sb + QL_OFF + SW128(r * 128 + c), qlb + (size_t)r * 128 + c);
    }

    auto load_chunk = [&](int j) {
        const int st = j & 1;
        const int f0 = j * 64;
#pragma unroll
        for (int i = 0; i < 2; i++) {
            int e = tid + i * 256;
            int r = e >> 3, c = (e & 7) * 16;
            CP_ASYNC16(sb + KH_OFF + st * 8192 + SW128(r * 128 + c),
                       khb + (size_t)(f0 + r) * 128 + c);
            CP_ASYNC16(sb + KL_OFF + st * 8192 + SW128(r * 128 + c),
                       klb + (size_t)(f0 + r) * 128 + c);
        }
#pragma unroll
        for (int i = 0; i < 4; i++) {
            int e = tid + i * 256;
            int r = e >> 4, c = (e & 15) * 16;
            CP_ASYNC16(sb + VH_OFF + st * 16384 + SW256(r * 256 + c),
                       vhb + (size_t)(f0 + r) * 256 + c);
            CP_ASYNC16(sb + VL_OFF + st * 16384 + SW256(r * 256 + c),
                       vlb + (size_t)(f0 + r) * 256 + c);
        }
    };

    load_chunk(0);
    CP_COMMIT();          // group 0 = q + chunk 0

    float of[16][4], ob[16][4];
#pragma unroll
    for (int nt = 0; nt < 16; nt++)
#pragma unroll
        for (int e = 0; e < 4; e++) { of[nt][e] = 0.f; ob[nt][e] = 0.f; }

    uint32_t qah[4][4], qal[4][4];    // q a-frags per k16 (loaded at j==0)
    float rs0 = 0.f, rs1 = 0.f;

    const int arow = lane & 15;
    const int acol = (lane >> 4) * 16;
    const int vrow = ((lane >> 3) & 1) * 8 + (lane & 7);

    for (int j = 0; j < NCHN; j++) {
        __syncthreads();                       // buffers from j-1 fully consumed
        if (j + 1 < NCHN) load_chunk(j + 1);
        CP_COMMIT();
        CP_WAIT(1);                            // chunk j resident
        __syncthreads();

        const int st = j & 1;

        if (j == 0) {
#pragma unroll
            for (int k16 = 0; k16 < 4; k16++) {
                uint32_t ah = sb + QH_OFF + SW128((wid*16 + arow) * 128 + k16*32 + acol);
                uint32_t al = sb + QL_OFF + SW128((wid*16 + arow) * 128 + k16*32 + acol);
                LDMATRIX_X4(qah[k16][0], qah[k16][1], qah[k16][2], qah[k16][3], ah);
                LDMATRIX_X4(qal[k16][0], qal[k16][1], qal[k16][2], qal[k16][3], al);
            }
        }

        // ---- S = q' @ k'^T (3-term split), 16 rows x 64 cols per warp ----
        float s[8][4];
#pragma unroll
        for (int nt = 0; nt < 8; nt++)
#pragma unroll
            for (int e = 0; e < 4; e++) s[nt][e] = 0.f;

        const uint32_t kbh = sb + KH_OFF + st * 8192;
        const uint32_t kbl = sb + KL_OFF + st * 8192;
#pragma unroll
        for (int k16 = 0; k16 < 4; k16++) {
#pragma unroll
            for (int ng = 0; ng < 4; ng++) {
                uint32_t h0, h1, h2, h3, l0, l1, l2, l3;
                uint32_t off = SW128((ng*16 + arow) * 128 + k16*32 + acol);
                LDMATRIX_X4(h0, h1, h2, h3, kbh + off);
                LDMATRIX_X4(l0, l1, l2, l3, kbl + off);
                MMA_BF16S(s[ng*2],   qah[k16], h0, h2);
                MMA_BF16S(s[ng*2+1], qah[k16], h1, h3);
                MMA_BF16S(s[ng*2],   qah[k16], l0, l2);
                MMA_BF16S(s[ng*2+1], qah[k16], l1, l3);
                MMA_BF16S(s[ng*2],   qal[k16], h0, h2);
                MMA_BF16S(s[ng*2+1], qal[k16], h1, h3);
            }
        }

        // ---- p = exp(s - 16), accumulate row sums ----
#pragma unroll
        for (int nt = 0; nt < 8; nt++) {
#pragma unroll
            for (int e = 0; e < 4; e++) {
                float p = __expf(fminf(s[nt][e], 88.f) - 16.f);
                s[nt][e] = p;
                if (e < 2) rs0 += p; else rs1 += p;
            }
        }

        // ---- O_block += P @ V (3-term split) ----
        const uint32_t vbh = sb + VH_OFF + st * 16384;
        const uint32_t vbl = sb + VL_OFF + st * 16384;
#pragma unroll
        for (int k16 = 0; k16 < 4; k16++) {
            uint32_t ph[4], pl[4];
            {
                float* t0 = s[2*k16];
                float* t1 = s[2*k16 + 1];
                float h00 = __bfloat162float(__float2bfloat16(t0[0]));
                float h01 = __bfloat162float(__float2bfloat16(t0[1]));
                float h02 = __bfloat162float(__float2bfloat16(t0[2]));
                float h03 = __bfloat162float(__float2bfloat16(t0[3]));
                float h10 = __bfloat162float(__float2bfloat16(t1[0]));
                float h11 = __bfloat162float(__float2bfloat16(t1[1]));
                float h12 = __bfloat162float(__float2bfloat16(t1[2]));
                float h13 = __bfloat162float(__float2bfloat16(t1[3]));
                ph[0] = pack_bf16(t0[0], t0[1]);
                ph[1] = pack_bf16(t0[2], t0[3]);
                ph[2] = pack_bf16(t1[0], t1[1]);
                ph[3] = pack_bf16(t1[2], t1[3]);
                pl[0] = pack_bf16(t0[0]-h00, t0[1]-h01);
                pl[1] = pack_bf16(t0[2]-h02, t0[3]-h03);
                pl[2] = pack_bf16(t1[0]-h10, t1[1]-h11);
                pl[3] = pack_bf16(t1[2]-h12, t1[3]-h13);
            }
#pragma unroll
            for (int ng = 0; ng < 8; ng++) {
                uint32_t off = SW256((k16*16 + vrow) * 256 + ng*32 + acol);
                uint32_t vh0, vh1, vh2, vh3, vl0, vl1, vl2, vl3;
                LDMATRIX_X4_T(vh0, vh1, vh2, vh3, vbh + off);
                LDMATRIX_X4_T(vl0, vl1, vl2, vl3, vbl + off);
                MMA_BF16S(ob[ng*2],   ph, vh0, vh1);
                MMA_BF16S(ob[ng*2+1], ph, vh2, vh3);
                MMA_BF16S(ob[ng*2],   ph, vl0, vl1);
                MMA_BF16S(ob[ng*2+1], ph, vl2, vl3);
                MMA_BF16S(ob[ng*2],   pl, vh0, vh1);
                MMA_BF16S(ob[ng*2+1], pl, vh2, vh3);
            }
        }

        // ---- end of 512-kv block: normalize and fold into O_final ----
        if ((j & 7) == 7) {
            rs0 += __shfl_xor_sync(0xffffffffu, rs0, 1);
            rs0 += __shfl_xor_sync(0xffffffffu, rs0, 2);
            rs1 += __shfl_xor_sync(0xffffffffu, rs1, 1);
            rs1 += __shfl_xor_sync(0xffffffffu, rs1, 2);
            float inv0 = 1.f / rs0, inv1 = 1.f / rs1;
#pragma unroll
            for (int nt = 0; nt < 16; nt++) {
                of[nt][0] += ob[nt][0] * inv0;
                of[nt][1] += ob[nt][1] * inv0;
                of[nt][2] += ob[nt][2] * inv1;
                of[nt][3] += ob[nt][3] * inv1;
                ob[nt][0] = 0.f; ob[nt][1] = 0.f; ob[nt][2] = 0.f; ob[nt][3] = 0.f;
            }
            rs0 = 0.f; rs1 = 0.f;
        }
    }

    // ---- epilogue: attn [B,H,S,DH] fp32 ----
    const int er = lane >> 2, ec = (lane & 3) * 2;
    float* obase = outp + (bh * SS + qr0 + wid*16) * DHH;
#pragma unroll
    for (int nt = 0; nt < 16; nt++) {
        int col = nt*8 + ec;
        float2 o0, o1;
        o0.x = of[nt][0]; o0.y = of[nt][1];
        o1.x = of[nt][2]; o1.y = of[nt][3];
        *(float2*)(obase + (size_t)er * DHH + col)       = o0;
        *(float2*)(obase + (size_t)(er + 8) * DHH + col) = o1;
    }
}

// ---------------------------------------------------------------------------
// Mixer (unchanged from R1)
// ---------------------------------------------------------------------------
#define MIX_SMEM_BYTES ((128*130 + 16*128) * 4)

__device__ __forceinline__ float gelu_tanh(float x) {
    float x3 = x * x * x;
    return 0.5f * x * (1.f + tanhf(0.7978845608028654f * (x + 0.044715f * x3)));
}

__global__ __launch_bounds__(256)
void mixer_kernel(const float* __restrict__ attn, const float* __restrict__ Wm,
                  const float* __restrict__ bm, float* __restrict__ mixed) {
    extern __shared__ float sm[];
    float* wm_s = sm;
    float* in_s = sm + 128*130;

    const int tid = threadIdx.x;
    const int R0 = blockIdx.x * 16;

    for (int i = tid; i < DHH*DHH; i += 256) {
        int d = i >> 7, c = i & 127;
        wm_s[d*130 + c] = Wm[i];
    }
    for (int i = tid; i < 16*DHH; i += 256)
        in_s[i] = attn[(size_t)R0 * DHH + i];
    __syncthreads();

    const int cp = (tid & 63) * 2;
    const int rg = tid >> 6;

    float acc[4][2];
#pragma unroll
    for (int i = 0; i < 4; i++) { acc[i][0] = 0.f; acc[i][1] = 0.f; }

#pragma unroll 8
    for (int d = 0; d < 128; d++) {
        float w0 = wm_s[d*130 + cp], w1 = wm_s[d*130 + cp + 1];
#pragma unroll
        for (int i = 0; i < 4; i++) {
            float a = in_s[(rg*4 + i)*128 + d];
            acc[i][0] += a * w0;
            acc[i][1] += a * w1;
        }
    }

    float b0 = bm[cp], b1 = bm[cp + 1];
#pragma unroll
    for (int i = 0; i < 4; i++) {
        int R = R0 + rg*4 + i;
        int b = R / (HH*SS);
        int rem = R % (HH*SS);
        int h = rem / SS, s = rem % SS;
        float2 o;
        o.x = gelu_tanh(acc[i][0] + b0);
        o.y = gelu_tanh(acc[i][1] + b1);
        *(float2*)&mixed[((size_t)b*SS + s)*EE + h*DHH + cp] = o;
    }
}

// ---------------------------------------------------------------------------
// Launch
// ---------------------------------------------------------------------------
extern "C" void kernel_launch(void* const* d_in, const int* in_sizes, int n_in,
                              void* d_out, int out_size) {
    const float* x   = (const float*)d_in[0];
    const float* Wq  = (const float*)d_in[1];
    const float* bq  = (const float*)d_in[2];
    const float* Wk  = (const float*)d_in[3];
    const float* bk_ = (const float*)d_in[4];
    const float* Wv  = (const float*)d_in[5];
    const float* bv_ = (const float*)d_in[6];
    const float* Wo  = (const float*)d_in[7];
    const float* bo  = (const float*)d_in[8];
    const float* Wql = (const float*)d_in[9];
    const float* bql = (const float*)d_in[10];
    const float* Wkl = (const float*)d_in[11];
    const float* bkl = (const float*)d_in[12];
    const float* Wm  = (const float*)d_in[13];
    const float* bm  = (const float*)d_in[14];
    float* outp = (float*)d_out;

    float* base = nullptr;
    cudaGetSymbolAddress((void**)&base, g_scratch);
    float* q    = base;
    float* k    = base + N_BSE;
    float* vv   = base + 2*N_BSE;
    float* attn = base + 3*N_BSE;
    float* mixd = base + 4*N_BSE;

    __nv_bfloat16* abf = nullptr;
    cudaGetSymbolAddress((void**)&abf, g_abf);
    __nv_bfloat16* wbf = nullptr;
    cudaGetSymbolAddress((void**)&wbf, g_wbf);
    __nv_bfloat16* wqb = wbf;
    __nv_bfloat16* wkb = wbf + (size_t)2048 * GK;
    __nv_bfloat16* wvb = wbf + (size_t)2 * 2048 * GK;
    __nv_bfloat16* wob = wbf + (size_t)3 * 2048 * GK;

    __nv_bfloat16* qk = nullptr;
    cudaGetSymbolAddress((void**)&qk, g_qk);
    __nv_bfloat16* qh  = qk;
    __nv_bfloat16* ql_ = qk + N_LAT;
    __nv_bfloat16* kh  = qk + 2*N_LAT;
    __nv_bfloat16* kl_ = qk + 3*N_LAT;
    __nv_bfloat16* vp = nullptr;
    cudaGetSymbolAddress((void**)&vp, g_v);
    __nv_bfloat16* vh  = vp;
    __nv_bfloat16* vl_ = vp + N_BSE;

    cudaFuncSetAttribute(gemm_mma,
        cudaFuncAttributeMaxDynamicSharedMemorySize, GEMM_SMEM);
    cudaFuncSetAttribute(attention_mma,
        cudaFuncAttributeMaxDynamicSharedMemorySize, ATT_SMEM);
    cudaFuncSetAttribute(mixer_kernel,
        cudaFuncAttributeMaxDynamicSharedMemorySize, MIX_SMEM_BYTES);

    dim3 cwg(64, 64);
    conv_a<<<MM * 2048 / 1024, 256>>>(x, abf);
    conv_w<<<cwg, 256>>>(Wq, wqb);
    conv_w<<<cwg, 256>>>(Wk, wkb);
    conv_w<<<cwg, 256>>>(Wv, wvb);
    conv_w<<<cwg, 256>>>(Wo, wob);

    dim3 gg(2048 / 128, MM / 128);   // (16, 32)
    gemm_mma<<<gg, 256, GEMM_SMEM>>>(abf, wqb, bq,  q);
    gemm_mma<<<gg, 256, GEMM_SMEM>>>(abf, wkb, bk_, k);
    gemm_mma<<<gg, 256, GEMM_SMEM>>>(abf, wvb, bv_, vv);

    latent_split<<<BB*SS, 256>>>(q, Wql, bql, qh, ql_, 0.125f);
    latent_split<<<BB*SS, 256>>>(k, Wkl, bkl, kh, kl_, 1.0f);
    conv_v<<<N_BSE / 1024, 256>>>(vv, vh, vl_);   // 8192 blocks (was 16384 — OOB bug)

    attention_mma<<<dim3(SS/128, HH, BB), 256, ATT_SMEM>>>(qh, ql_, kh, kl_, vh, vl_, attn);

    mixer_kernel<<<(BB*HH*SS)/16, 256, MIX_SMEM_BYTES>>>(attn, Wm, bm, mixd);

    conv_a<<<MM * 2048 / 1024, 256>>>(mixd, abf);
    gemm_mma<<<gg, 256, GEMM_SMEM>>>(abf, wob, bo, outp);
}

// round 8
// speedup vs baseline: 3.2498x; 1.2126x over previous
#include <cuda_runtime.h>
#include <cuda_bf16.h>
#include <math.h>
#include <stdint.h>

// Problem constants
#define BB  2
#define SS  2048
#define EE  2048
#define HH  16
#define DHH 128
#define LL  64
#define MM  (BB*SS)          // 4096 rows for the big GEMMs

#define N_BSE ((size_t)BB*SS*EE)       // 8388608
#define N_LAT ((size_t)BB*HH*SS*LL)    // 4194304

// fp32 scratch: attn_out lives at slot 3 (others now unused but kept for layout stability)
__device__ float g_scratch[5*8388608];
// bf16 split-stacked operands: A' [4096, 6144]; weight slots
__device__ __nv_bfloat16 g_abf[(size_t)4096 * 6144];
__device__ __nv_bfloat16 g_wbf[4][(size_t)2048 * 6144];
// attention operands: qh, ql, kh, kl planes [B,H,S,64]; vh, vl [B,H,S,128]
__device__ __nv_bfloat16 g_qk[4 * 4194304];
__device__ __nv_bfloat16 g_v[2 * 8388608];
// composed latent biases: bc[n] = b @ Wl + bl   (q, k)
__device__ float g_bc[2][1024];

// ===========================================================================
// Helpers
// ===========================================================================
__device__ __forceinline__ uint32_t smem_u32(const void* p) {
    uint32_t a;
    asm("{ .reg .u64 t; cvta.to.shared.u64 t, %1; cvt.u32.u64 %0, t; }"
        : "=r"(a) : "l"(p));
    return a;
}

#define CP_ASYNC16(sm, gp) \
    asm volatile("cp.async.cg.shared.global [%0], [%1], 16;" \
        :: "r"((uint32_t)(sm)), "l"(gp) : "memory")
#define CP_COMMIT() asm volatile("cp.async.commit_group;" ::: "memory")
#define CP_WAIT(n)  asm volatile("cp.async.wait_group %0;" :: "n"(n) : "memory")

// swizzles: 64B rows, 128B rows, 256B rows
#define SWZ64(o)  ((o) ^ (((o) >> 3) & 0x30))
#define SW128(o)  ((o) ^ (((o) >> 3) & 0x70))
#define SW256(o)  ((o) ^ (((o) >> 4) & 0x70))

#define LDMATRIX_X4(r0, r1, r2, r3, addr) \
    asm volatile("ldmatrix.sync.aligned.m8n8.x4.shared.b16 {%0,%1,%2,%3}, [%4];" \
        : "=r"(r0), "=r"(r1), "=r"(r2), "=r"(r3) : "r"(addr))

#define LDMATRIX_X4_T(r0, r1, r2, r3, addr) \
    asm volatile("ldmatrix.sync.aligned.m8n8.x4.trans.shared.b16 {%0,%1,%2,%3}, [%4];" \
        : "=r"(r0), "=r"(r1), "=r"(r2), "=r"(r3) : "r"(addr))

#define MMA_BF16(c, a, b) \
    asm volatile("mma.sync.aligned.m16n8k16.row.col.f32.bf16.bf16.f32 " \
        "{%0,%1,%2,%3}, {%4,%5,%6,%7}, {%8,%9}, {%0,%1,%2,%3};" \
        : "+f"((c)[0]), "+f"((c)[1]), "+f"((c)[2]), "+f"((c)[3]) \
        : "r"((a)[0]), "r"((a)[1]), "r"((a)[2]), "r"((a)[3]), \
          "r"((b)[0]), "r"((b)[1]))

#define MMA_BF16S(c, a, b0, b1) \
    asm volatile("mma.sync.aligned.m16n8k16.row.col.f32.bf16.bf16.f32 " \
        "{%0,%1,%2,%3}, {%4,%5,%6,%7}, {%8,%9}, {%0,%1,%2,%3};" \
        : "+f"((c)[0]), "+f"((c)[1]), "+f"((c)[2]), "+f"((c)[3]) \
        : "r"((a)[0]), "r"((a)[1]), "r"((a)[2]), "r"((a)[3]), \
          "r"(b0), "r"(b1))

__device__ __forceinline__ uint32_t pack_bf16(float lo, float hi) {
    uint32_t r;
    asm("cvt.rn.bf16x2.f32 %0, %1, %2;" : "=r"(r) : "f"(hi), "f"(lo));
    return r;
}

// ===========================================================================
// Conversion kernels
// ===========================================================================
#define GK  6144
#define GKB (GK * 2)   // row stride in bytes

// A' [M, 6144]: cols [0:2048)=hi, [2048:4096)=hi, [4096:6144)=lo
__global__ __launch_bounds__(256)
void conv_a(const float* __restrict__ in, __nv_bfloat16* __restrict__ out) {
    int i4 = (blockIdx.x * 256 + threadIdx.x) * 4;
    int m = i4 >> 11, k = i4 & 2047;
    float4 xv = *(const float4*)(in + (size_t)m * 2048 + k);
    __nv_bfloat16 h[4], l[4];
    float xs[4] = {xv.x, xv.y, xv.z, xv.w};
#pragma unroll
    for (int j = 0; j < 4; j++) {
        h[j] = __float2bfloat16(xs[j]);
        l[j] = __float2bfloat16(xs[j] - __bfloat162float(h[j]));
    }
    size_t base = (size_t)m * GK + k;
    __nv_bfloat162 h01, h23, l01, l23;
    h01.x = h[0]; h01.y = h[1]; h23.x = h[2]; h23.y = h[3];
    l01.x = l[0]; l01.y = l[1]; l23.x = l[2]; l23.y = l[3];
    *(__nv_bfloat162*)(out + base)            = h01;
    *(__nv_bfloat162*)(out + base + 2)        = h23;
    *(__nv_bfloat162*)(out + base + 2048)     = h01;
    *(__nv_bfloat162*)(out + base + 2050)     = h23;
    *(__nv_bfloat162*)(out + base + 4096)     = l01;
    *(__nv_bfloat162*)(out + base + 4098)     = l23;
}

// W [K=2048, N=2048] -> W'^T [N rows, 6144]: cols [0:2048)=hi, [2048:4096)=lo, [4096:6144)=hi
__global__ __launch_bounds__(256)
void conv_w(const float* __restrict__ W, __nv_bfloat16* __restrict__ out) {
    __shared__ float ts[32][33];
    const int tid = threadIdx.x;
    const int tx = tid & 31, ty = tid >> 5;
    const int n0 = blockIdx.x * 32, k0 = blockIdx.y * 32;
#pragma unroll
    for (int it = 0; it < 4; it++)
        ts[ty + it*8][tx] = W[(size_t)(k0 + ty + it*8) * 2048 + n0 + tx];
    __syncthreads();
#pragma unroll
    for (int it = 0; it < 4; it++) {
        int r = ty + it*8;
        float v = ts[tx][r];
        __nv_bfloat16 hi = __float2bfloat16(v);
        __nv_bfloat16 lo = __float2bfloat16(v - __bfloat162float(hi));
        size_t ob = (size_t)(n0 + r) * GK + k0 + tx;
        out[ob]        = hi;
        out[ob + 2048] = lo;
        out[ob + 4096] = hi;
    }
}

// ===========================================================================
// Composed latent weights: Wc^T[n=h*64+l, e] = sum_d Wl[d,l] * Wbig[e, h*128+d]
// written split-stacked [1024, 6144] (hi, lo, hi). grid (16 etiles, 16 heads).
// ===========================================================================
#define WC_SMEM (128*129*4 + 128*64*4)

__global__ __launch_bounds__(256)
void wc_kernel(const float* __restrict__ Wbig, const float* __restrict__ Wl,
               __nv_bfloat16* __restrict__ out) {
    extern __shared__ float wsm[];
    float* wq_s = wsm;              // [128][129]  [i][d]
    float* wl_s = wsm + 128*129;    // [128][64]   [d][l]
    const int tid = threadIdx.x;
    const int e0 = blockIdx.x * 128, h = blockIdx.y;

    for (int idx = tid; idx < 128*128; idx += 256) {
        int i = idx >> 7, d = idx & 127;
        wq_s[i*129 + d] = Wbig[(size_t)(e0 + i) * 2048 + h*128 + d];
    }
    for (int idx = tid; idx < 128*64; idx += 256)
        wl_s[idx] = Wl[idx];
    __syncthreads();

    const int i = tid & 127;
    const int lg = tid >> 7;          // 0..1
#pragma unroll 4
    for (int ll = 0; ll < 32; ll++) {
        int l = lg * 32 + ll;
        float acc = 0.f;
#pragma unroll 8
        for (int d = 0; d < 128; d++)
            acc += wq_s[i*129 + d] * wl_s[d*64 + l];
        __nv_bfloat16 hi = __float2bfloat16(acc);
        __nv_bfloat16 lo = __float2bfloat16(acc - __bfloat162float(hi));
        size_t ob = (size_t)(h*64 + l) * GK + e0 + i;
        out[ob]        = hi;
        out[ob + 2048] = lo;
        out[ob + 4096] = hi;
    }
}

// bc[n] = bl[l] + sum_d bbig[h*128+d] * Wl[d,l]
__global__ __launch_bounds__(256)
void wc_bias(const float* __restrict__ bbig, const float* __restrict__ Wl,
             const float* __restrict__ bl, float* __restrict__ bc) {
    int n = blockIdx.x * 256 + threadIdx.x;
    int h = n >> 6, l = n & 63;
    float acc = bl[l];
    for (int d = 0; d < 128; d++)
        acc += bbig[h*128 + d] * Wl[d*64 + l];
    bc[n] = acc;
}

// ===========================================================================
// mma.sync bf16 GEMM, templated epilogue.
// MODE 0: fp32 C = acc + bias
// MODE 1: vh/vl planes [B,H,S,128]
// MODE 2: elu+1, scale -> qh/ql (or kh/kl) planes [B,H,S,64]
// ===========================================================================
#define KITERS   192
#define STAGE_A  8192
#define STAGE_B  8192
#define B_OFF    (4 * STAGE_A)
#define GEMM_SMEM (B_OFF + 4 * STAGE_B)

template<int MODE>
__global__ __launch_bounds__(256, 2)
void gemm_k(const __nv_bfloat16* __restrict__ A, const __nv_bfloat16* __restrict__ Bt,
            const float* __restrict__ bias, float* __restrict__ C,
            __nv_bfloat16* __restrict__ P0, __nv_bfloat16* __restrict__ P1,
            float scale) {
    extern __shared__ char gsm[];
    uint32_t sb = smem_u32(gsm);
    const int tid = threadIdx.x;
    const int wid = tid >> 5, lane = tid & 31;
    const int m0 = blockIdx.y * 128, n0 = blockIdx.x * 128;
    const int wm0 = (wid >> 2) * 64;
    const int wn0 = (wid & 3) * 32;

    const char* Ab = (const char*)A + (size_t)m0 * GKB;
    const char* Bb = (const char*)Bt + (size_t)n0 * GKB;

    const int lr = tid >> 2;
    const int lq = tid & 3;

    auto load_chunk = [&](int j) {
        const int st = j & 3;
        uint32_t ab = sb + st * STAGE_A;
        uint32_t bb = sb + B_OFF + st * STAGE_B;
        const char* ag = Ab + (size_t)j * 64;
        const char* bg = Bb + (size_t)j * 64;
#pragma unroll
        for (int i = 0; i < 2; i++) {
            int r = lr + i * 64;
            CP_ASYNC16(ab + SWZ64(r * 64 + lq * 16), ag + (size_t)r * GKB + lq * 16);
        }
#pragma unroll
        for (int i = 0; i < 2; i++) {
            int r = lr + i * 64;
            CP_ASYNC16(bb + SWZ64(r * 64 + lq * 16), bg + (size_t)r * GKB + lq * 16);
        }
        CP_COMMIT();
    };

    float acc[4][4][4];
#pragma unroll
    for (int mt = 0; mt < 4; mt++)
#pragma unroll
        for (int nt = 0; nt < 4; nt++)
#pragma unroll
            for (int e = 0; e < 4; e++) acc[mt][nt][e] = 0.f;

    load_chunk(0);
    load_chunk(1);
    load_chunk(2);

    const int arow = lane & 15;
    const int acol = (lane >> 4) * 16;

    for (int it = 0; it < KITERS; it++) {
        CP_WAIT(2);
        __syncthreads();

        if (it + 3 < KITERS) load_chunk(it + 3);
        else                 CP_COMMIT();

        const int st = it & 3;
        uint32_t ab = sb + st * STAGE_A;
        uint32_t bb = sb + B_OFF + st * STAGE_B;

#pragma unroll
        for (int kk = 0; kk < 2; kk++) {
            uint32_t a[4][4];
            uint32_t b[4][2];
#pragma unroll
            for (int mt = 0; mt < 4; mt++) {
                uint32_t addr = ab + SWZ64((wm0 + mt*16 + arow) * 64 + kk*32 + acol);
                LDMATRIX_X4(a[mt][0], a[mt][1], a[mt][2], a[mt][3], addr);
            }
#pragma unroll
            for (int nb = 0; nb < 2; nb++) {
                uint32_t r0, r1, r2, r3;
                uint32_t addr = bb + SWZ64((wn0 + nb*16 + arow) * 64 + kk*32 + acol);
                LDMATRIX_X4(r0, r1, r2, r3, addr);
                b[nb*2+0][0] = r0; b[nb*2+0][1] = r2;
                b[nb*2+1][0] = r1; b[nb*2+1][1] = r3;
            }
#pragma unroll
            for (int mt = 0; mt < 4; mt++)
#pragma unroll
                for (int nt = 0; nt < 4; nt++)
                    MMA_BF16(acc[mt][nt], a[mt], b[nt]);
        }
        __syncthreads();
    }

    const int er = lane >> 2, ec = (lane & 3) * 2;
#pragma unroll
    for (int mt = 0; mt < 4; mt++) {
#pragma unroll
        for (int nt = 0; nt < 4; nt++) {
            int col = n0 + wn0 + nt*8 + ec;
            int row0 = m0 + wm0 + mt*16 + er;
            float b0 = bias[col], b1 = bias[col + 1];
            if (MODE == 0) {
                float2 o0, o1;
                o0.x = acc[mt][nt][0] + b0; o0.y = acc[mt][nt][1] + b1;
                o1.x = acc[mt][nt][2] + b0; o1.y = acc[mt][nt][3] + b1;
                *(float2*)(C + (size_t)row0 * 2048 + col)       = o0;
                *(float2*)(C + (size_t)(row0 + 8) * 2048 + col) = o1;
            } else if (MODE == 1) {
                int h = col >> 7, d = col & 127;
#pragma unroll
                for (int rr = 0; rr < 2; rr++) {
                    int row = row0 + rr*8;
                    int b = row >> 11, s = row & 2047;
                    float v0 = acc[mt][nt][rr*2+0] + b0;
                    float v1 = acc[mt][nt][rr*2+1] + b1;
                    __nv_bfloat162 hi2, lo2;
                    hi2.x = __float2bfloat16(v0);
                    hi2.y = __float2bfloat16(v1);
                    lo2.x = __float2bfloat16(v0 - __bfloat162float(hi2.x));
                    lo2.y = __float2bfloat16(v1 - __bfloat162float(hi2.y));
                    size_t ob = (((size_t)(b*HH + h)) * SS + s) * DHH + d;
                    *(__nv_bfloat162*)(P0 + ob) = hi2;
                    *(__nv_bfloat162*)(P1 + ob) = lo2;
                }
            } else {
                int h = col >> 6, l = col & 63;
#pragma unroll
                for (int rr = 0; rr < 2; rr++) {
                    int row = row0 + rr*8;
                    int b = row >> 11, s = row & 2047;
                    float a0 = acc[mt][nt][rr*2+0] + b0;
                    float a1 = acc[mt][nt][rr*2+1] + b1;
                    float r0 = ((a0 > 0.f) ? (a0 + 1.f) : __expf(a0)) * scale;
                    float r1 = ((a1 > 0.f) ? (a1 + 1.f) : __expf(a1)) * scale;
                    __nv_bfloat162 hi2, lo2;
                    hi2.x = __float2bfloat16(r0);
                    hi2.y = __float2bfloat16(r1);
                    lo2.x = __float2bfloat16(r0 - __bfloat162float(hi2.x));
                    lo2.y = __float2bfloat16(r1 - __bfloat162float(hi2.y));
                    size_t ob = (((size_t)(b*HH + h)) * SS + s) * LL + l;
                    *(__nv_bfloat162*)(P0 + ob) = hi2;
                    *(__nv_bfloat162*)(P1 + ob) = lo2;
                }
            }
        }
    }
}

// ===========================================================================
// Tensor-core block attention (unchanged from R6)
// ===========================================================================
#define QH_OFF  0
#define QL_OFF  16384
#define KH_OFF  32768
#define KL_OFF  49152
#define VH_OFF  65536
#define VL_OFF  98304
#define ATT_SMEM 131072
#define NCHN    32

__global__ __launch_bounds__(256, 1)
void attention_mma(const __nv_bfloat16* __restrict__ qh_g, const __nv_bfloat16* __restrict__ ql_g,
                   const __nv_bfloat16* __restrict__ kh_g, const __nv_bfloat16* __restrict__ kl_g,
                   const __nv_bfloat16* __restrict__ vh_g, const __nv_bfloat16* __restrict__ vl_g,
                   float* __restrict__ outp) {
    extern __shared__ char asmem[];
    uint32_t sb = smem_u32(asmem);
    const int tid = threadIdx.x, wid = tid >> 5, lane = tid & 31;
    const int qt = blockIdx.x, h = blockIdx.y, b = blockIdx.z;
    const int qr0 = qt * 128;
    const size_t bh = (size_t)(b * HH + h);

    const char* qhb = (const char*)(qh_g + (bh * SS + qr0) * LL);
    const char* qlb = (const char*)(ql_g + (bh * SS + qr0) * LL);
    const char* khb = (const char*)(kh_g + bh * SS * LL);
    const char* klb = (const char*)(kl_g + bh * SS * LL);
    const char* vhb = (const char*)(vh_g + bh * SS * DHH);
    const char* vlb = (const char*)(vl_g + bh * SS * DHH);

#pragma unroll
    for (int i = 0; i < 4; i++) {
        int e = tid + i * 256;
        int r = e >> 3, c = (e & 7) * 16;
        CP_ASYNC16(sb + QH_OFF + SW128(r * 128 + c), qhb + (size_t)r * 128 + c);
        CP_ASYNC16(sb + QL_OFF + SW128(r * 128 + c), qlb + (size_t)r * 128 + c);
    }

    auto load_chunk = [&](int j) {
        const int st = j & 1;
        const int f0 = j * 64;
#pragma unroll
        for (int i = 0; i < 2; i++) {
            int e = tid + i * 256;
            int r = e >> 3, c = (e & 7) * 16;
            CP_ASYNC16(sb + KH_OFF + st * 8192 + SW128(r * 128 + c),
                       khb + (size_t)(f0 + r) * 128 + c);
            CP_ASYNC16(sb + KL_OFF + st * 8192 + SW128(r * 128 + c),
                       klb + (size_t)(f0 + r) * 128 + c);
        }
#pragma unroll
        for (int i = 0; i < 4; i++) {
            int e = tid + i * 256;
            int r = e >> 4, c = (e & 15) * 16;
            CP_ASYNC16(sb + VH_OFF + st * 16384 + SW256(r * 256 + c),
                       vhb + (size_t)(f0 + r) * 256 + c);
            CP_ASYNC16(sb + VL_OFF + st * 16384 + SW256(r * 256 + c),
                       vlb + (size_t)(f0 + r) * 256 + c);
        }
    };

    load_chunk(0);
    CP_COMMIT();

    float of[16][4], ob[16][4];
#pragma unroll
    for (int nt = 0; nt < 16; nt++)
#pragma unroll
        for (int e = 0; e < 4; e++) { of[nt][e] = 0.f; ob[nt][e] = 0.f; }

    uint32_t qah[4][4], qal[4][4];
    float rs0 = 0.f, rs1 = 0.f;

    const int arow = lane & 15;
    const int acol = (lane >> 4) * 16;
    const int vrow = ((lane >> 3) & 1) * 8 + (lane & 7);

    for (int j = 0; j < NCHN; j++) {
        __syncthreads();
        if (j + 1 < NCHN) load_chunk(j + 1);
        CP_COMMIT();
        CP_WAIT(1);
        __syncthreads();

        const int st = j & 1;

        if (j == 0) {
#pragma unroll
            for (int k16 = 0; k16 < 4; k16++) {
                uint32_t ah = sb + QH_OFF + SW128((wid*16 + arow) * 128 + k16*32 + acol);
                uint32_t al = sb + QL_OFF + SW128((wid*16 + arow) * 128 + k16*32 + acol);
                LDMATRIX_X4(qah[k16][0], qah[k16][1], qah[k16][2], qah[k16][3], ah);
                LDMATRIX_X4(qal[k16][0], qal[k16][1], qal[k16][2], qal[k16][3], al);
            }
        }

        float s[8][4];
#pragma unroll
        for (int nt = 0; nt < 8; nt++)
#pragma unroll
            for (int e = 0; e < 4; e++) s[nt][e] = 0.f;

        const uint32_t kbh = sb + KH_OFF + st * 8192;
        const uint32_t kbl = sb + KL_OFF + st * 8192;
#pragma unroll
        for (int k16 = 0; k16 < 4; k16++) {
#pragma unroll
            for (int ng = 0; ng < 4; ng++) {
                uint32_t h0, h1, h2, h3, l0, l1, l2, l3;
                uint32_t off = SW128((ng*16 + arow) * 128 + k16*32 + acol);
                LDMATRIX_X4(h0, h1, h2, h3, kbh + off);
                LDMATRIX_X4(l0, l1, l2, l3, kbl + off);
                MMA_BF16S(s[ng*2],   qah[k16], h0, h2);
                MMA_BF16S(s[ng*2+1], qah[k16], h1, h3);
                MMA_BF16S(s[ng*2],   qah[k16], l0, l2);
                MMA_BF16S(s[ng*2+1], qah[k16], l1, l3);
                MMA_BF16S(s[ng*2],   qal[k16], h0, h2);
                MMA_BF16S(s[ng*2+1], qal[k16], h1, h3);
            }
        }

#pragma unroll
        for (int nt = 0; nt < 8; nt++) {
#pragma unroll
            for (int e = 0; e < 4; e++) {
                float p = __expf(fminf(s[nt][e], 88.f) - 16.f);
                s[nt][e] = p;
                if (e < 2) rs0 += p; else rs1 += p;
            }
        }

        const uint32_t vbh = sb + VH_OFF + st * 16384;
        const uint32_t vbl = sb + VL_OFF + st * 16384;
#pragma unroll
        for (int k16 = 0; k16 < 4; k16++) {
            uint32_t ph[4], pl[4];
            {
                float* t0 = s[2*k16];
                float* t1 = s[2*k16 + 1];
                float h00 = __bfloat162float(__float2bfloat16(t0[0]));
                float h01 = __bfloat162float(__float2bfloat16(t0[1]));
                float h02 = __bfloat162float(__float2bfloat16(t0[2]));
                float h03 = __bfloat162float(__float2bfloat16(t0[3]));
                float h10 = __bfloat162float(__float2bfloat16(t1[0]));
                float h11 = __bfloat162float(__float2bfloat16(t1[1]));
                float h12 = __bfloat162float(__float2bfloat16(t1[2]));
                float h13 = __bfloat162float(__float2bfloat16(t1[3]));
                ph[0] = pack_bf16(t0[0], t0[1]);
                ph[1] = pack_bf16(t0[2], t0[3]);
                ph[2] = pack_bf16(t1[0], t1[1]);
                ph[3] = pack_bf16(t1[2], t1[3]);
                pl[0] = pack_bf16(t0[0]-h00, t0[1]-h01);
                pl[1] = pack_bf16(t0[2]-h02, t0[3]-h03);
                pl[2] = pack_bf16(t1[0]-h10, t1[1]-h11);
                pl[3] = pack_bf16(t1[2]-h12, t1[3]-h13);
            }
#pragma unroll
            for (int ng = 0; ng < 8; ng++) {
                uint32_t off = SW256((k16*16 + vrow) * 256 + ng*32 + acol);
                uint32_t vh0, vh1, vh2, vh3, vl0, vl1, vl2, vl3;
                LDMATRIX_X4_T(vh0, vh1, vh2, vh3, vbh + off);
                LDMATRIX_X4_T(vl0, vl1, vl2, vl3, vbl + off);
                MMA_BF16S(ob[ng*2],   ph, vh0, vh1);
                MMA_BF16S(ob[ng*2+1], ph, vh2, vh3);
                MMA_BF16S(ob[ng*2],   ph, vl0, vl1);
                MMA_BF16S(ob[ng*2+1], ph, vl2, vl3);
                MMA_BF16S(ob[ng*2],   pl, vh0, vh1);
                MMA_BF16S(ob[ng*2+1], pl, vh2, vh3);
            }
        }

        if ((j & 7) == 7) {
            rs0 += __shfl_xor_sync(0xffffffffu, rs0, 1);
            rs0 += __shfl_xor_sync(0xffffffffu, rs0, 2);
            rs1 += __shfl_xor_sync(0xffffffffu, rs1, 1);
            rs1 += __shfl_xor_sync(0xffffffffu, rs1, 2);
            float inv0 = 1.f / rs0, inv1 = 1.f / rs1;
#pragma unroll
            for (int nt = 0; nt < 16; nt++) {
                of[nt][0] += ob[nt][0] * inv0;
                of[nt][1] += ob[nt][1] * inv0;
                of[nt][2] += ob[nt][2] * inv1;
                of[nt][3] += ob[nt][3] * inv1;
                ob[nt][0] = 0.f; ob[nt][1] = 0.f; ob[nt][2] = 0.f; ob[nt][3] = 0.f;
            }
            rs0 = 0.f; rs1 = 0.f;
        }
    }

    const int er = lane >> 2, ec = (lane & 3) * 2;
    float* obase = outp + (bh * SS + qr0 + wid*16) * DHH;
#pragma unroll
    for (int nt = 0; nt < 16; nt++) {
        int col = nt*8 + ec;
        float2 o0, o1;
        o0.x = of[nt][0]; o0.y = of[nt][1];
        o1.x = of[nt][2]; o1.y = of[nt][3];
        *(float2*)(obase + (size_t)er * DHH + col)       = o0;
        *(float2*)(obase + (size_t)(er + 8) * DHH + col) = o1;
    }
}

// ---------------------------------------------------------------------------
// Mixer: gelu(attn @ Wm + bm), writing split-stacked bf16 A' directly
// ---------------------------------------------------------------------------
#define MIX_SMEM_BYTES ((128*130 + 16*128) * 4)

__device__ __forceinline__ float gelu_tanh(float x) {
    float x3 = x * x * x;
    return 0.5f * x * (1.f + tanhf(0.7978845608028654f * (x + 0.044715f * x3)));
}

__global__ __launch_bounds__(256)
void mixer_split(const float* __restrict__ attn, const float* __restrict__ Wm,
                 const float* __restrict__ bm, __nv_bfloat16* __restrict__ abf) {
    extern __shared__ float sm[];
    float* wm_s = sm;
    float* in_s = sm + 128*130;

    const int tid = threadIdx.x;
    const int R0 = blockIdx.x * 16;

    for (int i = tid; i < DHH*DHH; i += 256) {
        int d = i >> 7, c = i & 127;
        wm_s[d*130 + c] = Wm[i];
    }
    for (int i = tid; i < 16*DHH; i += 256)
        in_s[i] = attn[(size_t)R0 * DHH + i];
    __syncthreads();

    const int cp = (tid & 63) * 2;
    const int rg = tid >> 6;

    float acc[4][2];
#pragma unroll
    for (int i = 0; i < 4; i++) { acc[i][0] = 0.f; acc[i][1] = 0.f; }

#pragma unroll 8
    for (int d = 0; d < 128; d++) {
        float w0 = wm_s[d*130 + cp], w1 = wm_s[d*130 + cp + 1];
#pragma unroll
        for (int i = 0; i < 4; i++) {
            float a = in_s[(rg*4 + i)*128 + d];
            acc[i][0] += a * w0;
            acc[i][1] += a * w1;
        }
    }

    float b0 = bm[cp], b1 = bm[cp + 1];
#pragma unroll
    for (int i = 0; i < 4; i++) {
        int R = R0 + rg*4 + i;                    // ((b*H + h)*S + s)
        int b = R / (HH*SS);
        int rem = R % (HH*SS);
        int h = rem / SS, s = rem % SS;
        float g0 = gelu_tanh(acc[i][0] + b0);
        float g1 = gelu_tanh(acc[i][1] + b1);
        __nv_bfloat162 hi2, lo2;
        hi2.x = __float2bfloat16(g0);
        hi2.y = __float2bfloat16(g1);
        lo2.x = __float2bfloat16(g0 - __bfloat162float(hi2.x));
        lo2.y = __float2bfloat16(g1 - __bfloat162float(hi2.y));
        size_t rb = ((size_t)b*SS + s) * GK + h*DHH + cp;
        *(__nv_bfloat162*)(abf + rb)        = hi2;   // A hi
        *(__nv_bfloat162*)(abf + rb + 2048) = hi2;   // A hi (dup)
        *(__nv_bfloat162*)(abf + rb + 4096) = lo2;   // A lo
    }
}

// ---------------------------------------------------------------------------
// Launch
// ---------------------------------------------------------------------------
extern "C" void kernel_launch(void* const* d_in, const int* in_sizes, int n_in,
                              void* d_out, int out_size) {
    const float* x   = (const float*)d_in[0];
    const float* Wq  = (const float*)d_in[1];
    const float* bq  = (const float*)d_in[2];
    const float* Wk  = (const float*)d_in[3];
    const float* bk_ = (const float*)d_in[4];
    const float* Wv  = (const float*)d_in[5];
    const float* bv_ = (const float*)d_in[6];
    const float* Wo  = (const float*)d_in[7];
    const float* bo  = (const float*)d_in[8];
    const float* Wql = (const float*)d_in[9];
    const float* bql = (const float*)d_in[10];
    const float* Wkl = (const float*)d_in[11];
    const float* bkl = (const float*)d_in[12];
    const float* Wm  = (const float*)d_in[13];
    const float* bm  = (const float*)d_in[14];
    float* outp = (float*)d_out;

    float* base = nullptr;
    cudaGetSymbolAddress((void**)&base, g_scratch);
    float* attn = base + 3*N_BSE;

    __nv_bfloat16* abf = nullptr;
    cudaGetSymbolAddress((void**)&abf, g_abf);
    __nv_bfloat16* wbf = nullptr;
    cudaGetSymbolAddress((void**)&wbf, g_wbf);
    __nv_bfloat16* wvb = wbf;
    __nv_bfloat16* wob = wbf + (size_t)2048 * GK;
    __nv_bfloat16* wcq = wbf + (size_t)2 * 2048 * GK;   // [1024, 6144]
    __nv_bfloat16* wck = wbf + (size_t)3 * 2048 * GK;

    __nv_bfloat16* qk = nullptr;
    cudaGetSymbolAddress((void**)&qk, g_qk);
    __nv_bfloat16* qh  = qk;
    __nv_bfloat16* ql_ = qk + N_LAT;
    __nv_bfloat16* kh  = qk + 2*N_LAT;
    __nv_bfloat16* kl_ = qk + 3*N_LAT;
    __nv_bfloat16* vp = nullptr;
    cudaGetSymbolAddress((void**)&vp, g_v);
    __nv_bfloat16* vh  = vp;
    __nv_bfloat16* vl_ = vp + N_BSE;

    float* bc = nullptr;
    cudaGetSymbolAddress((void**)&bc, g_bc);
    float* bcq = bc;
    float* bck = bc + 1024;

    cudaFuncSetAttribute(gemm_k<0>,
        cudaFuncAttributeMaxDynamicSharedMemorySize, GEMM_SMEM);
    cudaFuncSetAttribute(gemm_k<1>,
        cudaFuncAttributeMaxDynamicSharedMemorySize, GEMM_SMEM);
    cudaFuncSetAttribute(gemm_k<2>,
        cudaFuncAttributeMaxDynamicSharedMemorySize, GEMM_SMEM);
    cudaFuncSetAttribute(attention_mma,
        cudaFuncAttributeMaxDynamicSharedMemorySize, ATT_SMEM);
    cudaFuncSetAttribute(mixer_split,
        cudaFuncAttributeMaxDynamicSharedMemorySize, MIX_SMEM_BYTES);
    cudaFuncSetAttribute(wc_kernel,
        cudaFuncAttributeMaxDynamicSharedMemorySize, WC_SMEM);

    // input conversions / composed weights
    conv_a<<<MM * 2048 / 1024, 256>>>(x, abf);
    dim3 cwg(64, 64);
    conv_w<<<cwg, 256>>>(Wv, wvb);
    conv_w<<<cwg, 256>>>(Wo, wob);
    wc_kernel<<<dim3(16, 16), 256, WC_SMEM>>>(Wq, Wql, wcq);
    wc_kernel<<<dim3(16, 16), 256, WC_SMEM>>>(Wk, Wkl, wck);
    wc_bias<<<4, 256>>>(bq, Wql, bql, bcq);
    wc_bias<<<4, 256>>>(bk_, Wkl, bkl, bck);

    // projections (V full-width; Q/K composed to latent width with fused elu)
    gemm_k<1><<<dim3(16, 32), 256, GEMM_SMEM>>>(abf, wvb, bv_, nullptr, vh, vl_, 0.f);
    gemm_k<2><<<dim3(8, 32), 256, GEMM_SMEM>>>(abf, wcq, bcq, nullptr, qh, ql_, 0.125f);
    gemm_k<2><<<dim3(8, 32), 256, GEMM_SMEM>>>(abf, wck, bck, nullptr, kh, kl_, 1.0f);

    attention_mma<<<dim3(SS/128, HH, BB), 256, ATT_SMEM>>>(qh, ql_, kh, kl_, vh, vl_, attn);

    mixer_split<<<(BB*HH*SS)/16, 256, MIX_SMEM_BYTES>>>(attn, Wm, bm, abf);

    gemm_k<0><<<dim3(16, 32), 256, GEMM_SMEM>>>(abf, wob, bo, outp, nullptr, nullptr, 0.f);
}